// round 9
// baseline (speedup 1.0000x reference)
#include <cuda_runtime.h>
#include <cuda_bf16.h>
#include <cstdint>

// ---------------- problem constants ----------------
#define GRID     128
#define NTHREADS 256
#define SQ       2048
#define H        512
#define HBH      16384     // elements per (t, half) plane: 512 units x 32 batches
#define GPLD     34

// smem byte offsets
#define SMEM_SB   0        // 3 staging buffers x 8KB (hi 4KB | lo 4KB each)
#define SMEM_W1   24576    // layer1 Whh: hi 32KB | lo 32KB
#define SMEM_W2   90112    // layer2 (Wih2|Whh2): hi 64KB | lo 64KB
#define SMEM_GPA  221184   // 32 x GPLD x f32 (layer1 gates)
#define SMEM_GPB  225536   // 32 x GPLD x f32 (layer2 gates)
#define SMEM_E2S  229888   // 16 pairs x 32 rows f32
#define SMEM_BS   231936   // 64 f32 (L1 bias | L2 bias)
#define SMEM_TOT  232192

// ---------------- device scratch ----------------
__device__ __align__(16) __nv_bfloat16 g_h1h[(SQ + 1) * 2 * HBH];
__device__ __align__(16) __nv_bfloat16 g_h1l[(SQ + 1) * 2 * HBH];
__device__ __align__(16) __nv_bfloat16 g_h2h[2 * 2 * HBH];
__device__ __align__(16) __nv_bfloat16 g_h2l[2 * 2 * HBH];
__device__ __align__(16) float g_E2[16 * 4 * H];
__device__ int      g_pidx[SQ * 64];
__device__ unsigned g_isI32;
__device__ unsigned g_fA[2 * 64 * 32];   // h1-ready flags, 1/CTA, 128B apart
__device__ unsigned g_fB[2 * 64 * 32];   // h2-ready flags

__device__ __forceinline__ float sigmoidf_(float x) { return 1.f / (1.f + expf(-x)); }

// element offset inside one (t, half) plane: paired-k 128B rows, XOR swizzle
__device__ __forceinline__ int eoff_h(int k, int b) {
    return (k >> 1) * 64 + (k & 1) * 32 + ((((b >> 3) ^ ((k >> 1) & 3))) << 3) + (b & 7);
}

// ---------------- PTX helpers ----------------
__device__ __forceinline__ void ldmx4t(unsigned* r, uint32_t a) {
    asm volatile("ldmatrix.sync.aligned.m8n8.x4.trans.shared.b16 {%0,%1,%2,%3},[%4];"
                 : "=r"(r[0]), "=r"(r[1]), "=r"(r[2]), "=r"(r[3]) : "r"(a));
}
__device__ __forceinline__ void ldmx2t(unsigned* r, uint32_t a) {
    asm volatile("ldmatrix.sync.aligned.m8n8.x2.trans.shared.b16 {%0,%1},[%2];"
                 : "=r"(r[0]), "=r"(r[1]) : "r"(a));
}
__device__ __forceinline__ void mma16816(float* d, const unsigned* a, const unsigned* b) {
    asm volatile("mma.sync.aligned.m16n8k16.row.col.f32.bf16.bf16.f32 "
                 "{%0,%1,%2,%3},{%4,%5,%6,%7},{%8,%9},{%0,%1,%2,%3};"
                 : "+f"(d[0]), "+f"(d[1]), "+f"(d[2]), "+f"(d[3])
                 : "r"(a[0]), "r"(a[1]), "r"(a[2]), "r"(a[3]), "r"(b[0]), "r"(b[1]));
}
__device__ __forceinline__ void stg_bf16(__nv_bfloat16* p, __nv_bfloat16 v) {
    unsigned short u = *reinterpret_cast<unsigned short*>(&v);
    asm volatile("st.global.cg.u16 [%0], %1;" :: "l"(p), "h"(u) : "memory");
}
__device__ __forceinline__ float ldg_bf16(const __nv_bfloat16* p) {
    unsigned short u;
    asm volatile("ld.global.cg.u16 %0,[%1];" : "=h"(u) : "l"(p));
    __nv_bfloat16 b = *reinterpret_cast<__nv_bfloat16*>(&u);
    return __bfloat162float(b);
}
__device__ __forceinline__ void rel_store(unsigned* p, unsigned v) {
    asm volatile("st.release.gpu.global.u32 [%0],%1;" :: "l"(p), "r"(v) : "memory");
}
__device__ __forceinline__ unsigned acq_load(const unsigned* p) {
    unsigned v;
    asm volatile("ld.acquire.gpu.global.u32 %0,[%1];" : "=r"(v) : "l"(p) : "memory");
    return v;
}

#define CP_COMMIT() asm volatile("cp.async.commit_group;" ::: "memory")
#define CP_WAIT1()  asm volatile("cp.async.wait_group 1;" ::: "memory")

// plain (unguarded) stage of one 8KB chunk (hi 4KB + lo 4KB)
__device__ __forceinline__ void stage8(uint32_t sb, const __nv_bfloat16* gh,
                                       const __nv_bfloat16* gl, int tid) {
    uint32_t s = sb + (uint32_t)tid * 16u;
    asm volatile("cp.async.cg.shared.global [%0],[%1],16;"
                 :: "r"(s), "l"((const char*)gh + tid * 16) : "memory");
    asm volatile("cp.async.cg.shared.global [%0],[%1],16;"
                 :: "r"(s + 4096u), "l"((const char*)gl + tid * 16) : "memory");
}

// ---------------- setup kernels ----------------
__global__ void detect_reset() { g_isI32 = 0u; }

// int64 values in [0,4) -> odd u32 words all zero; int32 -> some nonzero.
__global__ void detect_dtype(const unsigned* __restrict__ w) {
    int i = blockIdx.x * blockDim.x + threadIdx.x;
    if (i < SQ * 64) {
        if ((i & 1) && w[i] != 0u) atomicOr(&g_isI32, 1u);
    }
}

__global__ void setup_misc(const void* __restrict__ inp_raw) {
    int i = blockIdx.x * blockDim.x + threadIdx.x;
    if (i < SQ * 64) {
        int s = i >> 6, b = i & 63;
        long long a, c;
        if (g_isI32) {
            const int* p = (const int*)inp_raw;
            a = p[b * SQ + s];
            c = p[(64 + b) * SQ + s];
        } else {
            const long long* p = (const long long*)inp_raw;
            a = p[(long long)b * SQ + s];
            c = p[(long long)(64 + b) * SQ + s];
        }
        g_pidx[s * 64 + b] = (int)(a * 4 + c);
    }
    __nv_bfloat16 z = __float2bfloat16(0.f);
    if (i < 2 * HBH) { g_h1h[i] = z; g_h1l[i] = z; }
    if (i < 4 * HBH) { g_h2h[i] = z; g_h2l[i] = z; }
}

__global__ void setup_e2(const float* __restrict__ embed, const float* __restrict__ Wih) {
    int flat = blockIdx.x * blockDim.x + threadIdx.x;
    int p = flat >> 11, r = flat & 2047;
    const float* e0 = embed + (p >> 2) * H;
    const float* e1 = embed + (p & 3) * H;
    const float* w  = Wih + (size_t)r * H;
    float s = 0.f;
    #pragma unroll 4
    for (int k = 0; k < H; k++) s += (e0[k] + e1[k]) * w[k];
    g_E2[p * 2048 + r] = s;
}

// ---------------- persistent merged-layer LSTM, dataflow-synced ----------------
__global__ __launch_bounds__(NTHREADS, 1)
void lstm_persist(const float* __restrict__ Wih, const float* __restrict__ Whh,
                  const float* __restrict__ bih, const float* __restrict__ bhh,
                  const float* __restrict__ ln_g, const float* __restrict__ ln_b,
                  const float* __restrict__ Wp,  const float* __restrict__ bp,
                  float* __restrict__ out)
{
    extern __shared__ char smem[];
    __nv_bfloat16* w1h = (__nv_bfloat16*)(smem + SMEM_W1);
    __nv_bfloat16* w1l = (__nv_bfloat16*)(smem + SMEM_W1 + 32768);
    __nv_bfloat16* w2h = (__nv_bfloat16*)(smem + SMEM_W2);
    __nv_bfloat16* w2l = (__nv_bfloat16*)(smem + SMEM_W2 + 65536);
    float* gpA = (float*)(smem + SMEM_GPA);
    float* gpB = (float*)(smem + SMEM_GPB);
    float* E2s = (float*)(smem + SMEM_E2S);
    float* bs  = (float*)(smem + SMEM_BS);
    uint32_t su = (uint32_t)__cvta_generic_to_shared(smem);
    const uint32_t SBu = su + SMEM_SB, W1u = su + SMEM_W1, W2u = su + SMEM_W2;
    __shared__ unsigned s_bA, s_bB;

    const int cta  = blockIdx.x;
    const int tid  = threadIdx.x;
    const int warp = tid >> 5, lane = tid & 31;
    const int ug   = cta >> 1;
    const int bh   = cta & 1;
    const int rn = warp >> 1;      // row n8-tile 0..3
    const int bm = warp & 1;       // batch m16-tile 0..1
    const int uu = tid >> 5, bl_e = tid & 31;

    const unsigned* fAh = g_fA + bh * 64 * 32;
    const unsigned* fBh = g_fB + bh * 64 * 32;
    unsigned* fA_own = g_fA + (bh * 64 + ug) * 32;
    unsigned* fB_own = g_fB + (bh * 64 + ug) * 32;

    // ldmatrix per-lane offsets (proven R6/R7 formulas)
    const int kA  = (lane & 7) + ((lane & 16) >> 1);
    const int jbA = bm * 2 + ((lane >> 3) & 1);
    const uint32_t aoff = (uint32_t)((kA >> 1) * 128 + (kA & 1) * 64 +
                                     ((jbA ^ ((kA >> 1) & 3)) << 4));
    const int kB  = lane & 15;
    const uint32_t bOff = (uint32_t)((kB >> 1) * 128 + (kB & 1) * 64 +
                                     ((rn ^ ((kB >> 1) & 3)) << 4));
    const int dr = rn * 8 + ((lane & 3) << 1);
    const int dc = bm * 16 + (lane >> 2);

    if (tid == 0) {
        s_bA = acq_load(fA_own);
        s_bB = acq_load(fB_own);
    }
    __syncthreads();
    const unsigned bA = s_bA, bB = s_bB;

    // ======== weight conversion ========
    for (int idx = tid; idx < 32 * H; idx += NTHREADS) {
        int r = idx >> 9, k = idx & (H - 1);
        int R = ((r >> 3) << 9) + (ug << 3) + (r & 7);
        float w = Whh[(size_t)R * H + k];
        __nv_bfloat16 hi = __float2bfloat16(w);
        __nv_bfloat16 lo = __float2bfloat16(w - __bfloat162float(hi));
        int e = (k >> 1) * 64 + (k & 1) * 32 + ((((r >> 3) ^ ((k >> 1) & 3))) << 3) + (r & 7);
        w1h[e] = hi; w1l[e] = lo;
    }
    {
        const float* Wih1 = Wih + (size_t)4 * H * H;
        const float* Whh1 = Whh + (size_t)4 * H * H;
        for (int idx = tid; idx < 32 * 2 * H; idx += NTHREADS) {
            int r = idx >> 10, k = idx & 1023;
            int R = ((r >> 3) << 9) + (ug << 3) + (r & 7);
            float w = (k < H) ? Wih1[(size_t)R * H + k] : Whh1[(size_t)R * H + (k - H)];
            __nv_bfloat16 hi = __float2bfloat16(w);
            __nv_bfloat16 lo = __float2bfloat16(w - __bfloat162float(hi));
            int e = (k >> 1) * 64 + (k & 1) * 32 + ((((r >> 3) ^ ((k >> 1) & 3))) << 3) + (r & 7);
            w2h[e] = hi; w2l[e] = lo;
        }
    }
    for (int idx = tid; idx < 512; idx += NTHREADS) {
        int p = idx >> 5, r = idx & 31;
        int R = ((r >> 3) << 9) + (ug << 3) + (r & 7);
        E2s[idx] = g_E2[p * 2048 + R];
    }
    if (tid < 32) {
        int R = ((tid >> 3) << 9) + (ug << 3) + (tid & 7);
        bs[tid]      = bih[R] + bhh[R];
        bs[tid + 32] = bih[2048 + R] + bhh[2048 + R];
    }
    __syncthreads();

    float cst1 = 0.f, cst2 = 0.f;
    const int GTOT = (SQ + 1) * 16;

    // pipeline fill: chunks g=0,1 (interval 0, h1 slot 0: flags already satisfied)
    stage8(SBu + 0u,    g_h1h + (size_t)bh * HBH,        g_h1l + (size_t)bh * HBH,        tid); CP_COMMIT();
    stage8(SBu + 8192u, g_h1h + (size_t)bh * HBH + 2048, g_h1l + (size_t)bh * HBH + 2048, tid); CP_COMMIT();

    for (int i = 0; i <= SQ; ++i) {
        float d1hh[4] = {0,0,0,0}, d1hl[4] = {0,0,0,0}, d1lh[4] = {0,0,0,0};
        float d2hh[4] = {0,0,0,0}, d2hl[4] = {0,0,0,0}, d2lh[4] = {0,0,0,0};
        const bool l1i = (i < SQ);
        const bool l2i = (i > 0);

        for (int c = 0; c < 16; ++c) {
            const int g2 = i * 16 + c + 2;

            // (A) producer-flag poll for chunk g2: 8 threads, one flag each
            if (g2 < GTOT && tid < 8) {
                int i2 = g2 >> 4, c2 = g2 & 15;
                const unsigned* f;
                unsigned tgt;
                if (c2 < 8) { f = fAh + ((c2 * 8 + tid) << 5); tgt = bA + (unsigned)i2; }
                else        { f = fBh + (((c2 - 8) * 8 + tid) << 5); tgt = bB + (unsigned)(i2 - 1); }
                unsigned cur;
                do { cur = acq_load(f); } while ((int)(cur - tgt) < 0);
            }

            // (B) chunk c data arrived
            CP_WAIT1();
            // (C) one sync: publishes acquires, chunk-c smem, frees buffer (c-1)
            __syncthreads();

            // (D) stage chunk g2 (buffer (g2)%3 == buffer of chunk c-1: free)
            if (g2 < GTOT) {
                int i2 = g2 >> 4, c2 = g2 & 15;
                uint32_t sb = SBu + (uint32_t)(g2 % 3) * 8192u;
                if (c2 < 8) {
                    const __nv_bfloat16* gh = g_h1h + ((size_t)i2 * 2 + bh) * HBH + c2 * 2048;
                    const __nv_bfloat16* gl = g_h1l + ((size_t)i2 * 2 + bh) * HBH + c2 * 2048;
                    stage8(sb, gh, gl, tid);
                } else {
                    int par = (i2 - 1) & 1;
                    const __nv_bfloat16* gh = g_h2h + ((size_t)par * 2 + bh) * HBH + (c2 - 8) * 2048;
                    const __nv_bfloat16* gl = g_h2l + ((size_t)par * 2 + bh) * HBH + (c2 - 8) * 2048;
                    stage8(sb, gh, gl, tid);
                }
            }
            CP_COMMIT();

            // (E) specials, off the staging critical path
            if (c == 0 && i >= 2) {
                // deferred L2 eltwise for interval i-1 (t=i-2); gpB visible via (C)
                float gv[4];
                #pragma unroll
                for (int gate = 0; gate < 4; ++gate) {
                    int r = (gate << 3) + uu;
                    gv[gate] = bs[32 + r] + gpB[r * GPLD + bl_e];
                }
                float ig = sigmoidf_(gv[0]);
                float fg = sigmoidf_(gv[1]);
                float gg = tanhf(gv[2]);
                float og = sigmoidf_(gv[3]);
                cst2 = fg * cst2 + ig * gg;
                float hv = og * tanhf(cst2);
                __nv_bfloat16 hi = __float2bfloat16(hv);
                __nv_bfloat16 lo = __float2bfloat16(hv - __bfloat162float(hi));
                size_t off = (size_t)(((i - 1) & 1) * 2 + bh) * HBH + eoff_h((ug << 3) + uu, bl_e);
                stg_bf16(g_h2h + off, hi);
                stg_bf16(g_h2l + off, lo);
            }
            if (c == 1 && i >= 2 && tid == 0)
                rel_store(fB_own, bB + (unsigned)(i - 1));   // ordered by (C) of this phase
            if (c == 8 && l1i) {
                // L1 eltwise for t=i; gpA written at phase 7, visible via (C)
                int p = g_pidx[i * 64 + bh * 32 + bl_e];
                float gv[4];
                #pragma unroll
                for (int gate = 0; gate < 4; ++gate) {
                    int r = (gate << 3) + uu;
                    gv[gate] = bs[r] + E2s[(p << 5) + r] + gpA[r * GPLD + bl_e];
                }
                float ig = sigmoidf_(gv[0]);
                float fg = sigmoidf_(gv[1]);
                float gg = tanhf(gv[2]);
                float og = sigmoidf_(gv[3]);
                cst1 = fg * cst1 + ig * gg;
                float hv = og * tanhf(cst1);
                __nv_bfloat16 hi = __float2bfloat16(hv);
                __nv_bfloat16 lo = __float2bfloat16(hv - __bfloat162float(hi));
                size_t off = (size_t)((i + 1) * 2 + bh) * HBH + eoff_h((ug << 3) + uu, bl_e);
                stg_bf16(g_h1h + off, hi);
                stg_bf16(g_h1l + off, lo);
            }
            if (c == 9 && l1i && tid == 0)
                rel_store(fA_own, bA + (unsigned)(i + 1));   // ordered by (C) of this phase

            // (F) MMA on chunk c
            uint32_t ab = SBu + (uint32_t)((i * 16 + c) % 3) * 8192u + aoff;
            if (c < 8) {
                uint32_t b1 = W1u + (uint32_t)c * 4096u + bOff;
                uint32_t b2 = W2u + (uint32_t)c * 4096u + bOff;
                #pragma unroll
                for (int t4 = 0; t4 < 4; ++t4) {
                    unsigned Ah[4], Al[4], Bf[2], Bl[2];
                    ldmx4t(Ah, ab);
                    ldmx4t(Al, ab + 4096u);
                    if (l1i) {
                        ldmx2t(Bf, b1);
                        ldmx2t(Bl, b1 + 32768u);
                        mma16816(d1hh, Ah, Bf);
                        mma16816(d1hl, Ah, Bl);
                        mma16816(d1lh, Al, Bf);
                    }
                    if (l2i) {
                        ldmx2t(Bf, b2);
                        ldmx2t(Bl, b2 + 65536u);
                        mma16816(d2hh, Ah, Bf);
                        mma16816(d2hl, Ah, Bl);
                        mma16816(d2lh, Al, Bf);
                    }
                    ab += 1024u; b1 += 1024u; b2 += 1024u;
                }
            } else if (l2i) {
                uint32_t b2 = W2u + (uint32_t)c * 4096u + bOff;
                #pragma unroll
                for (int t4 = 0; t4 < 4; ++t4) {
                    unsigned Ah[4], Al[4], Bf[2], Bl[2];
                    ldmx4t(Ah, ab);
                    ldmx4t(Al, ab + 4096u);
                    ldmx2t(Bf, b2);
                    ldmx2t(Bl, b2 + 65536u);
                    mma16816(d2hh, Ah, Bf);
                    mma16816(d2hl, Ah, Bl);
                    mma16816(d2lh, Al, Bf);
                    ab += 1024u; b2 += 1024u;
                }
            }

            if (c == 7 && l1i) {
                gpA[dr * GPLD + dc]           = d1hh[0] + d1hl[0] + d1lh[0];
                gpA[(dr + 1) * GPLD + dc]     = d1hh[1] + d1hl[1] + d1lh[1];
                gpA[dr * GPLD + dc + 8]       = d1hh[2] + d1hl[2] + d1lh[2];
                gpA[(dr + 1) * GPLD + dc + 8] = d1hh[3] + d1hl[3] + d1lh[3];
            }
            if (c == 15 && l2i) {
                gpB[dr * GPLD + dc]           = d2hh[0] + d2hl[0] + d2lh[0];
                gpB[(dr + 1) * GPLD + dc]     = d2hh[1] + d2hl[1] + d2lh[1];
                gpB[dr * GPLD + dc + 8]       = d2hh[2] + d2hl[2] + d2lh[2];
                gpB[(dr + 1) * GPLD + dc + 8] = d2hh[3] + d2hl[3] + d2lh[3];
            }
        }
    }

    // ======== epilogue: L2 eltwise for interval SQ (t=SQ-1) ========
    __syncthreads();
    {
        float gv[4];
        #pragma unroll
        for (int gate = 0; gate < 4; ++gate) {
            int r = (gate << 3) + uu;
            gv[gate] = bs[32 + r] + gpB[r * GPLD + bl_e];
        }
        float ig = sigmoidf_(gv[0]);
        float fg = sigmoidf_(gv[1]);
        float gg = tanhf(gv[2]);
        float og = sigmoidf_(gv[3]);
        cst2 = fg * cst2 + ig * gg;
        float hv = og * tanhf(cst2);
        __nv_bfloat16 hi = __float2bfloat16(hv);
        __nv_bfloat16 lo = __float2bfloat16(hv - __bfloat162float(hi));
        size_t off = (size_t)((SQ & 1) * 2 + bh) * HBH + eoff_h((ug << 3) + uu, bl_e);
        stg_bf16(g_h2h + off, hi);
        stg_bf16(g_h2l + off, lo);
    }
    __syncthreads();
    if (tid == 0) rel_store(fB_own, bB + (unsigned)SQ);

    // ======== head: LayerNorm + projection (final h2 at parity 0) ========
    if (cta < 8) {
        if (tid < 64) {
            const unsigned* f = fBh + tid * 32;
            unsigned tgt = bB + (unsigned)SQ;
            unsigned cur;
            do { cur = acq_load(f); } while ((int)(cur - tgt) < 0);
        }
        __syncthreads();

        int bl = ((cta >> 1) << 3) + warp;
        const __nv_bfloat16* h2h = g_h2h + (size_t)bh * HBH;
        const __nv_bfloat16* h2l = g_h2l + (size_t)bh * HBH;
        float s1 = 0.f, s2 = 0.f;
        for (int u = lane; u < H; u += 32) {
            int off = eoff_h(u, bl);
            float v = ldg_bf16(h2h + off) + ldg_bf16(h2l + off);
            s1 += v; s2 += v * v;
        }
        #pragma unroll
        for (int o = 16; o; o >>= 1) {
            s1 += __shfl_xor_sync(0xFFFFFFFFu, s1, o);
            s2 += __shfl_xor_sync(0xFFFFFFFFu, s2, o);
        }
        float mu  = s1 * (1.f / H);
        float var = s2 * (1.f / H) - mu * mu;
        float rs  = rsqrtf(var + 1e-5f);
        float acc = 0.f;
        for (int u = lane; u < H; u += 32) {
            int off = eoff_h(u, bl);
            float v  = ldg_bf16(h2h + off) + ldg_bf16(h2l + off);
            float hn = (v - mu) * rs * ln_g[u] + ln_b[u];
            acc += hn * Wp[u];
        }
        #pragma unroll
        for (int o = 16; o; o >>= 1) acc += __shfl_xor_sync(0xFFFFFFFFu, acc, o);
        if (lane == 0) out[bh * 32 + bl] = acc + bp[0];
    }
}

// ---------------- launch ----------------
extern "C" void kernel_launch(void* const* d_in, const int* in_sizes, int n_in,
                              void* d_out, int out_size) {
    const void*  inp   = d_in[0];
    const float* embed = (const float*)d_in[1];
    const float* Wih   = (const float*)d_in[2];
    const float* Whh   = (const float*)d_in[3];
    const float* bih   = (const float*)d_in[4];
    const float* bhh   = (const float*)d_in[5];
    const float* ln_g  = (const float*)d_in[6];
    const float* ln_b  = (const float*)d_in[7];
    const float* Wp    = (const float*)d_in[8];
    const float* bp    = (const float*)d_in[9];
    float* out = (float*)d_out;

    detect_reset<<<1, 1>>>();
    detect_dtype<<<512, 256>>>((const unsigned*)inp);
    setup_misc<<<512, 256>>>(inp);
    setup_e2<<<128, 256>>>(embed, Wih);

    cudaFuncSetAttribute(lstm_persist, cudaFuncAttributeMaxDynamicSharedMemorySize, SMEM_TOT);
    lstm_persist<<<GRID, NTHREADS, SMEM_TOT>>>(Wih, Whh, bih, bhh, ln_g, ln_b, Wp, bp, out);
}

// round 10
// speedup vs baseline: 1.3878x; 1.3878x over previous
#include <cuda_runtime.h>
#include <cuda_bf16.h>
#include <cstdint>

// ---------------- problem constants ----------------
#define GRID     128
#define NTHREADS 256
#define SQ       2048
#define H        512
#define HBH      16384     // elements per (t, half) plane: 512 units x 32 batches
#define GPLD     34

// smem byte offsets
#define SMEM_SB   0        // 3 staging buffers x 8KB (hi 4KB | lo 4KB each)
#define SMEM_W1   24576    // layer1 Whh: hi 32KB | lo 32KB
#define SMEM_W2   90112    // layer2 (Wih2|Whh2): hi 64KB | lo 64KB
#define SMEM_GPA  221184   // 32 x GPLD x f32 (layer1 gates)
#define SMEM_GPB  225536   // 32 x GPLD x f32 (layer2 gates)
#define SMEM_E2S  229888   // 16 pairs x 32 rows f32
#define SMEM_BS   231936   // 64 f32 (L1 bias | L2 bias)
#define SMEM_TOT  232192

// ---------------- device scratch ----------------
__device__ __align__(16) __nv_bfloat16 g_h1h[(SQ + 1) * 2 * HBH];
__device__ __align__(16) __nv_bfloat16 g_h1l[(SQ + 1) * 2 * HBH];
__device__ __align__(16) __nv_bfloat16 g_h2h[2 * 2 * HBH];
__device__ __align__(16) __nv_bfloat16 g_h2l[2 * 2 * HBH];
__device__ __align__(16) float g_E2[16 * 4 * H];
__device__ int      g_pidx[SQ * 64];
__device__ unsigned g_isI32;
// split arrive/wait generations (A: h1 ready, B: h2 ready), per half
__device__ unsigned g_cA1[2 * 8 * 32], g_cA2[2 * 32], g_genA[2 * 32];
__device__ unsigned g_cB1[2 * 8 * 32], g_cB2[2 * 32], g_genB[2 * 32];

__device__ __forceinline__ float sigmoidf_(float x) { return 1.f / (1.f + expf(-x)); }

// element offset inside one (t, half) plane: paired-k 128B rows, XOR swizzle
__device__ __forceinline__ int eoff_h(int k, int b) {
    return (k >> 1) * 64 + (k & 1) * 32 + ((((b >> 3) ^ ((k >> 1) & 3))) << 3) + (b & 7);
}

// ---------------- PTX helpers ----------------
__device__ __forceinline__ void ldmx4t(unsigned* r, uint32_t a) {
    asm volatile("ldmatrix.sync.aligned.m8n8.x4.trans.shared.b16 {%0,%1,%2,%3},[%4];"
                 : "=r"(r[0]), "=r"(r[1]), "=r"(r[2]), "=r"(r[3]) : "r"(a));
}
__device__ __forceinline__ void ldmx2t(unsigned* r, uint32_t a) {
    asm volatile("ldmatrix.sync.aligned.m8n8.x2.trans.shared.b16 {%0,%1},[%2];"
                 : "=r"(r[0]), "=r"(r[1]) : "r"(a));
}
__device__ __forceinline__ void mma16816(float* d, const unsigned* a, const unsigned* b) {
    asm volatile("mma.sync.aligned.m16n8k16.row.col.f32.bf16.bf16.f32 "
                 "{%0,%1,%2,%3},{%4,%5,%6,%7},{%8,%9},{%0,%1,%2,%3};"
                 : "+f"(d[0]), "+f"(d[1]), "+f"(d[2]), "+f"(d[3])
                 : "r"(a[0]), "r"(a[1]), "r"(a[2]), "r"(a[3]), "r"(b[0]), "r"(b[1]));
}
__device__ __forceinline__ void stg_bf16(__nv_bfloat16* p, __nv_bfloat16 v) {
    unsigned short u = *reinterpret_cast<unsigned short*>(&v);
    asm volatile("st.global.cg.u16 [%0], %1;" :: "l"(p), "h"(u) : "memory");
}
__device__ __forceinline__ float ldg_bf16(const __nv_bfloat16* p) {
    unsigned short u;
    asm volatile("ld.global.cg.u16 %0,[%1];" : "=h"(u) : "l"(p));
    __nv_bfloat16 b = *reinterpret_cast<__nv_bfloat16*>(&u);
    return __bfloat162float(b);
}
__device__ __forceinline__ unsigned acq_load(const unsigned* p) {
    unsigned v;
    asm volatile("ld.acquire.gpu.global.u32 %0,[%1];" : "=r"(v) : "l"(p) : "memory");
    return v;
}

// hierarchical arrive: 8 groups of 8, root of 8, post gen=val on completion.
// Counters self-reset; next round's arrivals provably start only after post.
__device__ __forceinline__ void arrive_gen(unsigned* c1, unsigned* c2,
                                           unsigned* gen, unsigned val) {
    unsigned p1;
    asm volatile("atom.acq_rel.gpu.global.add.u32 %0,[%1],%2;"
                 : "=r"(p1) : "l"(c1), "r"(1u) : "memory");
    if (p1 == 7u) {
        asm volatile("st.relaxed.gpu.global.u32 [%0],%1;" :: "l"(c1), "r"(0u) : "memory");
        unsigned p2;
        asm volatile("atom.acq_rel.gpu.global.add.u32 %0,[%1],%2;"
                     : "=r"(p2) : "l"(c2), "r"(1u) : "memory");
        if (p2 == 7u) {
            asm volatile("st.relaxed.gpu.global.u32 [%0],%1;" :: "l"(c2), "r"(0u) : "memory");
            asm volatile("st.release.gpu.global.u32 [%0],%1;" :: "l"(gen), "r"(val) : "memory");
        }
    }
}

#define CP_COMMIT() asm volatile("cp.async.commit_group;" ::: "memory")
#define CP_WAIT1()  asm volatile("cp.async.wait_group 1;" ::: "memory")

// plain stage of one 8KB chunk (hi 4KB + lo 4KB)
__device__ __forceinline__ void stage8(uint32_t sb, const __nv_bfloat16* gh,
                                       const __nv_bfloat16* gl, int tid) {
    uint32_t s = sb + (uint32_t)tid * 16u;
    asm volatile("cp.async.cg.shared.global [%0],[%1],16;"
                 :: "r"(s), "l"((const char*)gh + tid * 16) : "memory");
    asm volatile("cp.async.cg.shared.global [%0],[%1],16;"
                 :: "r"(s + 4096u), "l"((const char*)gl + tid * 16) : "memory");
}

// ---------------- setup kernels ----------------
__global__ void detect_reset() {
    g_isI32 = 0u;
    for (int h = 0; h < 2; h++) {
        for (int g = 0; g < 8; g++) { g_cA1[(h * 8 + g) * 32] = 0u; g_cB1[(h * 8 + g) * 32] = 0u; }
        g_cA2[h * 32] = 0u; g_genA[h * 32] = 0u;
        g_cB2[h * 32] = 0u; g_genB[h * 32] = 0u;
    }
}

// int64 values in [0,4) -> odd u32 words all zero; int32 -> some nonzero.
__global__ void detect_dtype(const unsigned* __restrict__ w) {
    int i = blockIdx.x * blockDim.x + threadIdx.x;
    if (i < SQ * 64) {
        if ((i & 1) && w[i] != 0u) atomicOr(&g_isI32, 1u);
    }
}

__global__ void setup_misc(const void* __restrict__ inp_raw) {
    int i = blockIdx.x * blockDim.x + threadIdx.x;
    if (i < SQ * 64) {
        int s = i >> 6, b = i & 63;
        long long a, c;
        if (g_isI32) {
            const int* p = (const int*)inp_raw;
            a = p[b * SQ + s];
            c = p[(64 + b) * SQ + s];
        } else {
            const long long* p = (const long long*)inp_raw;
            a = p[(long long)b * SQ + s];
            c = p[(long long)(64 + b) * SQ + s];
        }
        g_pidx[s * 64 + b] = (int)(a * 4 + c);
    }
    __nv_bfloat16 z = __float2bfloat16(0.f);
    if (i < 2 * HBH) { g_h1h[i] = z; g_h1l[i] = z; }
    if (i < 4 * HBH) { g_h2h[i] = z; g_h2l[i] = z; }
}

__global__ void setup_e2(const float* __restrict__ embed, const float* __restrict__ Wih) {
    int flat = blockIdx.x * blockDim.x + threadIdx.x;
    int p = flat >> 11, r = flat & 2047;
    const float* e0 = embed + (p >> 2) * H;
    const float* e1 = embed + (p & 3) * H;
    const float* w  = Wih + (size_t)r * H;
    float s = 0.f;
    #pragma unroll 4
    for (int k = 0; k < H; k++) s += (e0[k] + e1[k]) * w[k];
    g_E2[p * 2048 + r] = s;
}

// ---------------- persistent merged-layer LSTM ----------------
__global__ __launch_bounds__(NTHREADS, 1)
void lstm_persist(const float* __restrict__ Wih, const float* __restrict__ Whh,
                  const float* __restrict__ bih, const float* __restrict__ bhh,
                  const float* __restrict__ ln_g, const float* __restrict__ ln_b,
                  const float* __restrict__ Wp,  const float* __restrict__ bp,
                  float* __restrict__ out)
{
    extern __shared__ char smem[];
    __nv_bfloat16* w1h = (__nv_bfloat16*)(smem + SMEM_W1);
    __nv_bfloat16* w1l = (__nv_bfloat16*)(smem + SMEM_W1 + 32768);
    __nv_bfloat16* w2h = (__nv_bfloat16*)(smem + SMEM_W2);
    __nv_bfloat16* w2l = (__nv_bfloat16*)(smem + SMEM_W2 + 65536);
    float* gpA = (float*)(smem + SMEM_GPA);
    float* gpB = (float*)(smem + SMEM_GPB);
    float* E2s = (float*)(smem + SMEM_E2S);
    float* bs  = (float*)(smem + SMEM_BS);
    uint32_t su = (uint32_t)__cvta_generic_to_shared(smem);
    const uint32_t SBu = su + SMEM_SB, W1u = su + SMEM_W1, W2u = su + SMEM_W2;

    const int cta  = blockIdx.x;
    const int tid  = threadIdx.x;
    const int warp = tid >> 5, lane = tid & 31;
    const int ug   = cta >> 1;
    const int bh   = cta & 1;
    const int grp  = ug >> 3;
    const int rn = warp >> 1;      // row n8-tile 0..3
    const int bm = warp & 1;       // batch m16-tile 0..1
    const int uu = tid >> 5, bl_e = tid & 31;

    unsigned* cA1 = g_cA1 + (bh * 8 + grp) * 32;
    unsigned* cA2 = g_cA2 + bh * 32;
    unsigned* gA  = g_genA + bh * 32;
    unsigned* cB1 = g_cB1 + (bh * 8 + grp) * 32;
    unsigned* cB2 = g_cB2 + bh * 32;
    unsigned* gB  = g_genB + bh * 32;

    // ldmatrix per-lane offsets (proven R6/R7 formulas)
    const int kA  = (lane & 7) + ((lane & 16) >> 1);
    const int jbA = bm * 2 + ((lane >> 3) & 1);
    const uint32_t aoff = (uint32_t)((kA >> 1) * 128 + (kA & 1) * 64 +
                                     ((jbA ^ ((kA >> 1) & 3)) << 4));
    const int kB  = lane & 15;
    const uint32_t bOff = (uint32_t)((kB >> 1) * 128 + (kB & 1) * 64 +
                                     ((rn ^ ((kB >> 1) & 3)) << 4));
    const int dr = rn * 8 + ((lane & 3) << 1);
    const int dc = bm * 16 + (lane >> 2);

    // ======== weight conversion ========
    for (int idx = tid; idx < 32 * H; idx += NTHREADS) {
        int r = idx >> 9, k = idx & (H - 1);
        int R = ((r >> 3) << 9) + (ug << 3) + (r & 7);
        float w = Whh[(size_t)R * H + k];
        __nv_bfloat16 hi = __float2bfloat16(w);
        __nv_bfloat16 lo = __float2bfloat16(w - __bfloat162float(hi));
        int e = (k >> 1) * 64 + (k & 1) * 32 + ((((r >> 3) ^ ((k >> 1) & 3))) << 3) + (r & 7);
        w1h[e] = hi; w1l[e] = lo;
    }
    {
        const float* Wih1 = Wih + (size_t)4 * H * H;
        const float* Whh1 = Whh + (size_t)4 * H * H;
        for (int idx = tid; idx < 32 * 2 * H; idx += NTHREADS) {
            int r = idx >> 10, k = idx & 1023;
            int R = ((r >> 3) << 9) + (ug << 3) + (r & 7);
            float w = (k < H) ? Wih1[(size_t)R * H + k] : Whh1[(size_t)R * H + (k - H)];
            __nv_bfloat16 hi = __float2bfloat16(w);
            __nv_bfloat16 lo = __float2bfloat16(w - __bfloat162float(hi));
            int e = (k >> 1) * 64 + (k & 1) * 32 + ((((r >> 3) ^ ((k >> 1) & 3))) << 3) + (r & 7);
            w2h[e] = hi; w2l[e] = lo;
        }
    }
    for (int idx = tid; idx < 512; idx += NTHREADS) {
        int p = idx >> 5, r = idx & 31;
        int R = ((r >> 3) << 9) + (ug << 3) + (r & 7);
        E2s[idx] = g_E2[p * 2048 + R];
    }
    if (tid < 32) {
        int R = ((tid >> 3) << 9) + (ug << 3) + (tid & 7);
        bs[tid]      = bih[R] + bhh[R];
        bs[tid + 32] = bih[2048 + R] + bhh[2048 + R];
    }
    __syncthreads();

    float cst1 = 0.f, cst2 = 0.f;
    const int GTOT = (SQ + 1) * 16;

    // pipeline fill: chunks g=0,1 (interval 0, h1 slot 0 ready from setup)
    stage8(SBu + 0u,    g_h1h + (size_t)bh * HBH,        g_h1l + (size_t)bh * HBH,        tid); CP_COMMIT();
    stage8(SBu + 8192u, g_h1h + (size_t)bh * HBH + 2048, g_h1l + (size_t)bh * HBH + 2048, tid); CP_COMMIT();

    for (int i = 0; i <= SQ; ++i) {
        float d1hh[4] = {0,0,0,0}, d1hl[4] = {0,0,0,0}, d1lh[4] = {0,0,0,0};
        float d2hh[4] = {0,0,0,0}, d2hl[4] = {0,0,0,0}, d2lh[4] = {0,0,0,0};
        const bool l1i = (i < SQ);
        const bool l2i = (i > 0);

        for (int c = 0; c < 16; ++c) {
            const int g2 = i * 16 + c + 2;

            // (B) chunk c arrived; (C) one sync: visibility + frees buffer (c-1)
            CP_WAIT1();
            __syncthreads();

            // split-barrier waits: single poll, gates NEXT phase's staging
            if (c == 5 && i >= 2 && tid == 0) {           // gate h2 chunks (stage from c==6)
                unsigned tgt = (unsigned)(i - 1);
                while ((int)(acq_load(gB) - tgt) < 0) { }
            }
            if (c == 13 && i < SQ && tid == 0) {          // gate next interval h1 chunks
                unsigned tgt = (unsigned)(i + 1);
                while ((int)(acq_load(gA) - tgt) < 0) { }
            }

            // (D) stage chunk g2 (buffer (g2)%3 freed by this phase's sync)
            if (g2 < GTOT) {
                int i2 = g2 >> 4, c2 = g2 & 15;
                uint32_t sb = SBu + (uint32_t)(g2 % 3) * 8192u;
                if (c2 < 8) {
                    const __nv_bfloat16* gh = g_h1h + ((size_t)i2 * 2 + bh) * HBH + c2 * 2048;
                    const __nv_bfloat16* gl = g_h1l + ((size_t)i2 * 2 + bh) * HBH + c2 * 2048;
                    stage8(sb, gh, gl, tid);
                } else {
                    int par = (i2 - 1) & 1;
                    const __nv_bfloat16* gh = g_h2h + ((size_t)par * 2 + bh) * HBH + (c2 - 8) * 2048;
                    const __nv_bfloat16* gl = g_h2l + ((size_t)par * 2 + bh) * HBH + (c2 - 8) * 2048;
                    stage8(sb, gh, gl, tid);
                }
            }
            CP_COMMIT();

            // (E) eltwise + arrivals (ride the existing phase syncs)
            if (c == 0 && i >= 2) {
                // deferred L2 eltwise for t=i-2 (gpB of interval i-1, visible via sync)
                float gv[4];
                #pragma unroll
                for (int gate = 0; gate < 4; ++gate) {
                    int r = (gate << 3) + uu;
                    gv[gate] = bs[32 + r] + gpB[r * GPLD + bl_e];
                }
                float ig = sigmoidf_(gv[0]);
                float fg = sigmoidf_(gv[1]);
                float gg = tanhf(gv[2]);
                float og = sigmoidf_(gv[3]);
                cst2 = fg * cst2 + ig * gg;
                float hv = og * tanhf(cst2);
                __nv_bfloat16 hi = __float2bfloat16(hv);
                __nv_bfloat16 lo = __float2bfloat16(hv - __bfloat162float(hi));
                size_t off = (size_t)(((i - 1) & 1) * 2 + bh) * HBH + eoff_h((ug << 3) + uu, bl_e);
                stg_bf16(g_h2h + off, hi);
                stg_bf16(g_h2l + off, lo);
            }
            if (c == 1 && i >= 2 && tid == 0)
                arrive_gen(cB1, cB2, gB, (unsigned)(i - 1));   // ordered by this phase's sync
            if (c == 8 && l1i) {
                // L1 eltwise for t=i (gpA written phase 7, visible via sync)
                int p = g_pidx[i * 64 + bh * 32 + bl_e];
                float gv[4];
                #pragma unroll
                for (int gate = 0; gate < 4; ++gate) {
                    int r = (gate << 3) + uu;
                    gv[gate] = bs[r] + E2s[(p << 5) + r] + gpA[r * GPLD + bl_e];
                }
                float ig = sigmoidf_(gv[0]);
                float fg = sigmoidf_(gv[1]);
                float gg = tanhf(gv[2]);
                float og = sigmoidf_(gv[3]);
                cst1 = fg * cst1 + ig * gg;
                float hv = og * tanhf(cst1);
                __nv_bfloat16 hi = __float2bfloat16(hv);
                __nv_bfloat16 lo = __float2bfloat16(hv - __bfloat162float(hi));
                size_t off = (size_t)((i + 1) * 2 + bh) * HBH + eoff_h((ug << 3) + uu, bl_e);
                stg_bf16(g_h1h + off, hi);
                stg_bf16(g_h1l + off, lo);
            }
            if (c == 9 && l1i && tid == 0)
                arrive_gen(cA1, cA2, gA, (unsigned)(i + 1));   // ordered by this phase's sync

            // (F) MMA on chunk c
            uint32_t ab = SBu + (uint32_t)((i * 16 + c) % 3) * 8192u + aoff;
            if (c < 8) {
                uint32_t b1 = W1u + (uint32_t)c * 4096u + bOff;
                uint32_t b2 = W2u + (uint32_t)c * 4096u + bOff;
                #pragma unroll
                for (int t4 = 0; t4 < 4; ++t4) {
                    unsigned Ah[4], Al[4], Bf[2], Bl[2];
                    ldmx4t(Ah, ab);
                    ldmx4t(Al, ab + 4096u);
                    if (l1i) {
                        ldmx2t(Bf, b1);
                        ldmx2t(Bl, b1 + 32768u);
                        mma16816(d1hh, Ah, Bf);
                        mma16816(d1hl, Ah, Bl);
                        mma16816(d1lh, Al, Bf);
                    }
                    if (l2i) {
                        ldmx2t(Bf, b2);
                        ldmx2t(Bl, b2 + 65536u);
                        mma16816(d2hh, Ah, Bf);
                        mma16816(d2hl, Ah, Bl);
                        mma16816(d2lh, Al, Bf);
                    }
                    ab += 1024u; b1 += 1024u; b2 += 1024u;
                }
            } else if (l2i) {
                uint32_t b2 = W2u + (uint32_t)c * 4096u + bOff;
                #pragma unroll
                for (int t4 = 0; t4 < 4; ++t4) {
                    unsigned Ah[4], Al[4], Bf[2], Bl[2];
                    ldmx4t(Ah, ab);
                    ldmx4t(Al, ab + 4096u);
                    ldmx2t(Bf, b2);
                    ldmx2t(Bl, b2 + 65536u);
                    mma16816(d2hh, Ah, Bf);
                    mma16816(d2hl, Ah, Bl);
                    mma16816(d2lh, Al, Bf);
                    ab += 1024u; b2 += 1024u;
                }
            }

            if (c == 7 && l1i) {
                gpA[dr * GPLD + dc]           = d1hh[0] + d1hl[0] + d1lh[0];
                gpA[(dr + 1) * GPLD + dc]     = d1hh[1] + d1hl[1] + d1lh[1];
                gpA[dr * GPLD + dc + 8]       = d1hh[2] + d1hl[2] + d1lh[2];
                gpA[(dr + 1) * GPLD + dc + 8] = d1hh[3] + d1hl[3] + d1lh[3];
            }
            if (c == 15 && l2i) {
                gpB[dr * GPLD + dc]           = d2hh[0] + d2hl[0] + d2lh[0];
                gpB[(dr + 1) * GPLD + dc]     = d2hh[1] + d2hl[1] + d2lh[1];
                gpB[dr * GPLD + dc + 8]       = d2hh[2] + d2hl[2] + d2lh[2];
                gpB[(dr + 1) * GPLD + dc + 8] = d2hh[3] + d2hl[3] + d2lh[3];
            }
        }
    }

    // ======== epilogue: L2 eltwise for t=SQ-1 ========
    __syncthreads();
    {
        float gv[4];
        #pragma unroll
        for (int gate = 0; gate < 4; ++gate) {
            int r = (gate << 3) + uu;
            gv[gate] = bs[32 + r] + gpB[r * GPLD + bl_e];
        }
        float ig = sigmoidf_(gv[0]);
        float fg = sigmoidf_(gv[1]);
        float gg = tanhf(gv[2]);
        float og = sigmoidf_(gv[3]);
        cst2 = fg * cst2 + ig * gg;
        float hv = og * tanhf(cst2);
        __nv_bfloat16 hi = __float2bfloat16(hv);
        __nv_bfloat16 lo = __float2bfloat16(hv - __bfloat162float(hi));
        size_t off = (size_t)((SQ & 1) * 2 + bh) * HBH + eoff_h((ug << 3) + uu, bl_e);
        stg_bf16(g_h2h + off, hi);
        stg_bf16(g_h2l + off, lo);
    }
    __syncthreads();
    if (tid == 0) arrive_gen(cB1, cB2, gB, (unsigned)SQ);

    // ======== head: LayerNorm + projection (final h2 at parity 0) ========
    if (cta < 8) {
        if (tid == 0) {
            while ((int)(acq_load(gB) - (unsigned)SQ) < 0) { }
        }
        __syncthreads();

        int bl = ((cta >> 1) << 3) + warp;
        const __nv_bfloat16* h2h = g_h2h + (size_t)bh * HBH;
        const __nv_bfloat16* h2l = g_h2l + (size_t)bh * HBH;
        float s1 = 0.f, s2 = 0.f;
        for (int u = lane; u < H; u += 32) {
            int off = eoff_h(u, bl);
            float v = ldg_bf16(h2h + off) + ldg_bf16(h2l + off);
            s1 += v; s2 += v * v;
        }
        #pragma unroll
        for (int o = 16; o; o >>= 1) {
            s1 += __shfl_xor_sync(0xFFFFFFFFu, s1, o);
            s2 += __shfl_xor_sync(0xFFFFFFFFu, s2, o);
        }
        float mu  = s1 * (1.f / H);
        float var = s2 * (1.f / H) - mu * mu;
        float rs  = rsqrtf(var + 1e-5f);
        float acc = 0.f;
        for (int u = lane; u < H; u += 32) {
            int off = eoff_h(u, bl);
            float v  = ldg_bf16(h2h + off) + ldg_bf16(h2l + off);
            float hn = (v - mu) * rs * ln_g[u] + ln_b[u];
            acc += hn * Wp[u];
        }
        #pragma unroll
        for (int o = 16; o; o >>= 1) acc += __shfl_xor_sync(0xFFFFFFFFu, acc, o);
        if (lane == 0) out[bh * 32 + bl] = acc + bp[0];
    }
}

// ---------------- launch ----------------
extern "C" void kernel_launch(void* const* d_in, const int* in_sizes, int n_in,
                              void* d_out, int out_size) {
    const void*  inp   = d_in[0];
    const float* embed = (const float*)d_in[1];
    const float* Wih   = (const float*)d_in[2];
    const float* Whh   = (const float*)d_in[3];
    const float* bih   = (const float*)d_in[4];
    const float* bhh   = (const float*)d_in[5];
    const float* ln_g  = (const float*)d_in[6];
    const float* ln_b  = (const float*)d_in[7];
    const float* Wp    = (const float*)d_in[8];
    const float* bp    = (const float*)d_in[9];
    float* out = (float*)d_out;

    detect_reset<<<1, 1>>>();
    detect_dtype<<<512, 256>>>((const unsigned*)inp);
    setup_misc<<<512, 256>>>(inp);
    setup_e2<<<128, 256>>>(embed, Wih);

    cudaFuncSetAttribute(lstm_persist, cudaFuncAttributeMaxDynamicSharedMemorySize, SMEM_TOT);
    lstm_persist<<<GRID, NTHREADS, SMEM_TOT>>>(Wih, Whh, bih, bhh, ln_g, ln_b, Wp, bp, out);
}

// round 12
// speedup vs baseline: 2.2763x; 1.6402x over previous
#include <cuda_runtime.h>
#include <cuda_fp16.h>
#include <cstdint>

// ---------------- problem constants ----------------
#define GRID     128
#define NTHREADS 256
#define SQ       2048
#define H        512
#define HBH      16384     // elements per (t, half) plane: 512 units x 32 batches
#define GPLD     34

// smem byte offsets
#define SMEM_SB   0        // 3 staging buffers x 4KB (h fp16), K=64 chunks
#define SMEM_W1   12288    // layer1 Whh: hi 32KB | lo 32KB
#define SMEM_W2   77824    // layer2 (Wih2|Whh2): hi 64KB | lo 64KB
#define SMEM_GPA  208896   // 32 x GPLD x f32 (layer1 gates)
#define SMEM_GPB  213248   // 32 x GPLD x f32 (layer2 gates)
#define SMEM_E2S  217600   // 16 pairs x 32 rows f32
#define SMEM_BS   219648   // 64 f32 (L1 bias | L2 bias)
#define SMEM_TOT  219904

// ---------------- device scratch ----------------
__device__ __align__(16) __half g_h1h[(SQ + 1) * 2 * HBH];
__device__ __align__(16) __half g_h2h[2 * 2 * HBH];
__device__ __align__(16) float g_E2[16 * 4 * H];
__device__ int      g_pidx[SQ * 64];
__device__ unsigned g_isI32;
__device__ unsigned g_c1[2 * 8 * 32];   // group counters (128B apart)
__device__ unsigned g_c2[2 * 32];       // root counters
__device__ unsigned g_gen[2 * 32];      // per-half generation

__device__ __forceinline__ float sigmoidf_(float x) { return 1.f / (1.f + expf(-x)); }

// element offset inside one (t, half) plane: paired-k 128B rows, XOR swizzle
__device__ __forceinline__ int eoff_h(int k, int b) {
    return (k >> 1) * 64 + (k & 1) * 32 + ((((b >> 3) ^ ((k >> 1) & 3))) << 3) + (b & 7);
}

// ---------------- PTX helpers ----------------
__device__ __forceinline__ void ldmx4t(unsigned* r, uint32_t a) {
    asm volatile("ldmatrix.sync.aligned.m8n8.x4.trans.shared.b16 {%0,%1,%2,%3},[%4];"
                 : "=r"(r[0]), "=r"(r[1]), "=r"(r[2]), "=r"(r[3]) : "r"(a));
}
__device__ __forceinline__ void ldmx2t(unsigned* r, uint32_t a) {
    asm volatile("ldmatrix.sync.aligned.m8n8.x2.trans.shared.b16 {%0,%1},[%2];"
                 : "=r"(r[0]), "=r"(r[1]) : "r"(a));
}
__device__ __forceinline__ void mma16816(float* d, const unsigned* a, const unsigned* b) {
    asm volatile("mma.sync.aligned.m16n8k16.row.col.f32.f16.f16.f32 "
                 "{%0,%1,%2,%3},{%4,%5,%6,%7},{%8,%9},{%0,%1,%2,%3};"
                 : "+f"(d[0]), "+f"(d[1]), "+f"(d[2]), "+f"(d[3])
                 : "r"(a[0]), "r"(a[1]), "r"(a[2]), "r"(a[3]), "r"(b[0]), "r"(b[1]));
}
__device__ __forceinline__ void stg_h16(__half* p, __half v) {
    unsigned short u = *reinterpret_cast<unsigned short*>(&v);
    asm volatile("st.global.cg.u16 [%0], %1;" :: "l"(p), "h"(u) : "memory");
}
__device__ __forceinline__ float ldg_h16(const __half* p) {
    unsigned short u;
    asm volatile("ld.global.cg.u16 %0,[%1];" : "=h"(u) : "l"(p));
    __half b = *reinterpret_cast<__half*>(&u);
    return __half2float(b);
}

// Hierarchical per-half barrier (proven R6/R7). Replay-safe via base snapshot.
__device__ __forceinline__ void half_barrier(unsigned target, int half, int grp) {
    __syncthreads();
    if (threadIdx.x == 0) {
        unsigned* c1 = &g_c1[(half * 8 + grp) * 32];
        unsigned* c2 = &g_c2[half * 32];
        unsigned* gv = &g_gen[half * 32];
        unsigned p1;
        asm volatile("atom.acq_rel.gpu.global.add.u32 %0,[%1],%2;"
                     : "=r"(p1) : "l"(c1), "r"(1u) : "memory");
        bool done = false;
        if (p1 == 7u) {
            asm volatile("st.relaxed.gpu.global.u32 [%0],%1;" :: "l"(c1), "r"(0u) : "memory");
            unsigned p2;
            asm volatile("atom.acq_rel.gpu.global.add.u32 %0,[%1],%2;"
                         : "=r"(p2) : "l"(c2), "r"(1u) : "memory");
            if (p2 == 7u) {
                asm volatile("st.relaxed.gpu.global.u32 [%0],%1;" :: "l"(c2), "r"(0u) : "memory");
                asm volatile("st.release.gpu.global.u32 [%0],%1;" :: "l"(gv), "r"(target) : "memory");
                done = true;
            }
        }
        if (!done) {
            unsigned cur;
            do {
                asm volatile("ld.acquire.gpu.global.u32 %0,[%1];" : "=r"(cur) : "l"(gv) : "memory");
            } while ((int)(cur - target) < 0);
        }
    }
    __syncthreads();
}

// stage one 4KB chunk (h fp16); 1 cp.async per thread
__device__ __forceinline__ void stage4(uint32_t sb, const __half* gh, int tid) {
    asm volatile("cp.async.cg.shared.global [%0],[%1],16;"
                 :: "r"(sb + (uint32_t)tid * 16u), "l"((const char*)gh + tid * 16) : "memory");
}
#define CP_COMMIT() asm volatile("cp.async.commit_group;" ::: "memory")
#define CP_WAIT2()  asm volatile("cp.async.wait_group 2;" ::: "memory")
#define CP_WAIT1()  asm volatile("cp.async.wait_group 1;" ::: "memory")
#define CP_WAIT0()  asm volatile("cp.async.wait_group 0;" ::: "memory")

// ---------------- setup kernels ----------------
__global__ void detect_reset() { g_isI32 = 0u; }

// int64 values in [0,4) -> odd u32 words all zero; int32 -> some nonzero.
__global__ void detect_dtype(const unsigned* __restrict__ w) {
    int i = blockIdx.x * blockDim.x + threadIdx.x;
    if (i < SQ * 64) {
        if ((i & 1) && w[i] != 0u) atomicOr(&g_isI32, 1u);
    }
}

__global__ void setup_misc(const void* __restrict__ inp_raw) {
    int i = blockIdx.x * blockDim.x + threadIdx.x;
    if (i < SQ * 64) {
        int s = i >> 6, b = i & 63;
        long long a, c;
        if (g_isI32) {
            const int* p = (const int*)inp_raw;
            a = p[b * SQ + s];
            c = p[(64 + b) * SQ + s];
        } else {
            const long long* p = (const long long*)inp_raw;
            a = p[(long long)b * SQ + s];
            c = p[(long long)(64 + b) * SQ + s];
        }
        g_pidx[s * 64 + b] = (int)(a * 4 + c);
    }
    __half z = __float2half(0.f);
    if (i < 2 * HBH) g_h1h[i] = z;
    if (i < 4 * HBH) g_h2h[i] = z;
}

__global__ void setup_e2(const float* __restrict__ embed, const float* __restrict__ Wih) {
    int flat = blockIdx.x * blockDim.x + threadIdx.x;
    int p = flat >> 11, r = flat & 2047;
    const float* e0 = embed + (p >> 2) * H;
    const float* e1 = embed + (p & 3) * H;
    const float* w  = Wih + (size_t)r * H;
    float s = 0.f;
    #pragma unroll 4
    for (int k = 0; k < H; k++) s += (e0[k] + e1[k]) * w[k];
    g_E2[p * 2048 + r] = s;
}

// ---------------- persistent merged-layer LSTM kernel ----------------
// CTA = (ug = cta>>1 unit-group 0..63, bh = cta&1 batch half). Interval i:
// layer1[t=i] (i<SQ) and layer2[t=i-1] (i>0), sharing staged h1 slot-i chunks.
// One hierarchical half-barrier per interval (proven R7 structure).
__global__ __launch_bounds__(NTHREADS, 1)
void lstm_persist(const float* __restrict__ Wih, const float* __restrict__ Whh,
                  const float* __restrict__ bih, const float* __restrict__ bhh,
                  const float* __restrict__ ln_g, const float* __restrict__ ln_b,
                  const float* __restrict__ Wp,  const float* __restrict__ bp,
                  float* __restrict__ out)
{
    extern __shared__ char smem[];
    __half* w1h = (__half*)(smem + SMEM_W1);
    __half* w1l = (__half*)(smem + SMEM_W1 + 32768);
    __half* w2h = (__half*)(smem + SMEM_W2);
    __half* w2l = (__half*)(smem + SMEM_W2 + 65536);
    float* gpA = (float*)(smem + SMEM_GPA);
    float* gpB = (float*)(smem + SMEM_GPB);
    float* E2s = (float*)(smem + SMEM_E2S);
    float* bs  = (float*)(smem + SMEM_BS);
    uint32_t su = (uint32_t)__cvta_generic_to_shared(smem);
    const uint32_t SBu = su + SMEM_SB, W1u = su + SMEM_W1, W2u = su + SMEM_W2;
    __shared__ unsigned s_base;

    const int cta  = blockIdx.x;
    const int tid  = threadIdx.x;
    const int warp = tid >> 5, lane = tid & 31;
    const int ug   = cta >> 1;
    const int bh   = cta & 1;
    const int grp  = ug >> 3;
    const int rn = warp >> 1;      // row n8-tile 0..3
    const int bm = warp & 1;       // batch m16-tile 0..1
    const int uu = tid >> 5, bl_e = tid & 31;

    // ldmatrix per-lane offsets (proven R6/R7 formulas)
    const int kA  = (lane & 7) + ((lane & 16) >> 1);
    const int jbA = bm * 2 + ((lane >> 3) & 1);
    const uint32_t aoff = (uint32_t)((kA >> 1) * 128 + (kA & 1) * 64 +
                                     ((jbA ^ ((kA >> 1) & 3)) << 4));
    const int kB  = lane & 15;
    const uint32_t bOff = (uint32_t)((kB >> 1) * 128 + (kB & 1) * 64 +
                                     ((rn ^ ((kB >> 1) & 3)) << 4));
    const int dr = rn * 8 + ((lane & 3) << 1);
    const int dc = bm * 16 + (lane >> 2);

    if (tid == 0) {
        unsigned b_;
        asm volatile("ld.relaxed.gpu.global.u32 %0,[%1];" : "=r"(b_) : "l"(&g_gen[bh * 32]) : "memory");
        s_base = b_;
    }
    __syncthreads();
    unsigned gen = s_base;

    // ======== weight conversion: W1 (Whh layer0), W2 (Wih1|Whh1) ========
    for (int idx = tid; idx < 32 * H; idx += NTHREADS) {
        int r = idx >> 9, k = idx & (H - 1);
        int R = ((r >> 3) << 9) + (ug << 3) + (r & 7);
        float w = Whh[(size_t)R * H + k];
        __half hi = __float2half(w);
        __half lo = __float2half(w - __half2float(hi));
        int e = (k >> 1) * 64 + (k & 1) * 32 + ((((r >> 3) ^ ((k >> 1) & 3))) << 3) + (r & 7);
        w1h[e] = hi; w1l[e] = lo;
    }
    {
        const float* Wih1 = Wih + (size_t)4 * H * H;
        const float* Whh1 = Whh + (size_t)4 * H * H;
        for (int idx = tid; idx < 32 * 2 * H; idx += NTHREADS) {
            int r = idx >> 10, k = idx & 1023;
            int R = ((r >> 3) << 9) + (ug << 3) + (r & 7);
            float w = (k < H) ? Wih1[(size_t)R * H + k] : Whh1[(size_t)R * H + (k - H)];
            __half hi = __float2half(w);
            __half lo = __float2half(w - __half2float(hi));
            int e = (k >> 1) * 64 + (k & 1) * 32 + ((((r >> 3) ^ ((k >> 1) & 3))) << 3) + (r & 7);
            w2h[e] = hi; w2l[e] = lo;
        }
    }
    for (int idx = tid; idx < 512; idx += NTHREADS) {
        int p = idx >> 5, r = idx & 31;
        int R = ((r >> 3) << 9) + (ug << 3) + (r & 7);
        E2s[idx] = g_E2[p * 2048 + R];
    }
    if (tid < 32) {
        int R = ((tid >> 3) << 9) + (ug << 3) + (tid & 7);
        bs[tid]      = bih[R] + bhh[R];
        bs[tid + 32] = bih[2048 + R] + bhh[2048 + R];
    }
    __syncthreads();

    float cst1 = 0.f, cst2 = 0.f;

    for (int i = 0; i <= SQ; ++i) {
        const bool doL1 = (i < SQ);
        const bool doL2 = (i > 0);
        const int  nch  = doL2 ? 16 : 8;
        const size_t base1 = (size_t)(i * 2 + bh) * HBH;
        const size_t base2 = (size_t)((((i - 1) & 1)) * 2 + bh) * HBH;

        // issue first 3 chunks
        #pragma unroll
        for (int n = 0; n < 3; ++n) {
            const __half* gh = (n < 8) ? (g_h1h + base1 + n * 2048)
                                       : (g_h2h + base2 + (n - 8) * 2048);
            stage4(SBu + (n % 3) * 4096u, gh, tid);
            CP_COMMIT();
        }

        float d1hh[4] = {0,0,0,0}, d1hl[4] = {0,0,0,0};
        float d2hh[4] = {0,0,0,0}, d2hl[4] = {0,0,0,0};

        for (int c = 0; c < nch; ++c) {
            int rem = nch - 1 - c;
            if (rem >= 2)      { CP_WAIT2(); }
            else if (rem == 1) { CP_WAIT1(); }
            else               { CP_WAIT0(); }
            __syncthreads();

            uint32_t ab  = SBu + (uint32_t)(c % 3) * 4096u + aoff;
            uint32_t b1  = W1u + (uint32_t)c * 4096u + bOff;
            uint32_t b2  = W2u + (uint32_t)c * 4096u + bOff;
            const bool l1 = (c < 8) && doL1;
            #pragma unroll
            for (int t = 0; t < 4; ++t) {
                unsigned Ah[4], Bh_[2], Bl_[2];
                ldmx4t(Ah, ab);
                if (l1) {
                    ldmx2t(Bh_, b1);
                    ldmx2t(Bl_, b1 + 32768u);
                    mma16816(d1hh, Ah, Bh_);
                    mma16816(d1hl, Ah, Bl_);
                }
                if (doL2) {
                    ldmx2t(Bh_, b2);
                    ldmx2t(Bl_, b2 + 65536u);
                    mma16816(d2hh, Ah, Bh_);
                    mma16816(d2hl, Ah, Bl_);
                }
                ab += 1024u; b1 += 1024u; b2 += 1024u;
            }
            __syncthreads();

            int n = c + 3;
            if (n < nch) {
                const __half* gh = (n < 8) ? (g_h1h + base1 + n * 2048)
                                           : (g_h2h + base2 + (n - 8) * 2048);
                stage4(SBu + (uint32_t)(n % 3) * 4096u, gh, tid);
                CP_COMMIT();
            }
        }

        // write gate partials
        if (doL1) {
            gpA[dr * GPLD + dc]           = d1hh[0] + d1hl[0];
            gpA[(dr + 1) * GPLD + dc]     = d1hh[1] + d1hl[1];
            gpA[dr * GPLD + dc + 8]       = d1hh[2] + d1hl[2];
            gpA[(dr + 1) * GPLD + dc + 8] = d1hh[3] + d1hl[3];
        }
        if (doL2) {
            gpB[dr * GPLD + dc]           = d2hh[0] + d2hl[0];
            gpB[(dr + 1) * GPLD + dc]     = d2hh[1] + d2hl[1];
            gpB[dr * GPLD + dc + 8]       = d2hh[2] + d2hl[2];
            gpB[(dr + 1) * GPLD + dc + 8] = d2hh[3] + d2hl[3];
        }
        __syncthreads();

        // eltwise layer1
        if (doL1) {
            int p = g_pidx[i * 64 + bh * 32 + bl_e];
            float gv[4];
            #pragma unroll
            for (int gate = 0; gate < 4; ++gate) {
                int r = (gate << 3) + uu;
                gv[gate] = bs[r] + E2s[(p << 5) + r] + gpA[r * GPLD + bl_e];
            }
            float ig = sigmoidf_(gv[0]);
            float fg = sigmoidf_(gv[1]);
            float gg = tanhf(gv[2]);
            float og = sigmoidf_(gv[3]);
            cst1 = fg * cst1 + ig * gg;
            float hv = og * tanhf(cst1);
            size_t off = (size_t)((i + 1) * 2 + bh) * HBH + eoff_h((ug << 3) + uu, bl_e);
            stg_h16(g_h1h + off, __float2half(hv));
        }
        // eltwise layer2
        if (doL2) {
            float gv[4];
            #pragma unroll
            for (int gate = 0; gate < 4; ++gate) {
                int r = (gate << 3) + uu;
                gv[gate] = bs[32 + r] + gpB[r * GPLD + bl_e];
            }
            float ig = sigmoidf_(gv[0]);
            float fg = sigmoidf_(gv[1]);
            float gg = tanhf(gv[2]);
            float og = sigmoidf_(gv[3]);
            cst2 = fg * cst2 + ig * gg;
            float hv = og * tanhf(cst2);
            size_t off = (size_t)((i & 1) * 2 + bh) * HBH + eoff_h((ug << 3) + uu, bl_e);
            stg_h16(g_h2h + off, __float2half(hv));
        }
        half_barrier(++gen, bh, grp);
    }

    // ======== head: LayerNorm + projection (final h2 at parity 0) ========
    if (cta < 8) {
        int half = cta & 1;
        int bl = ((cta >> 1) << 3) + warp;
        const __half* h2h = g_h2h + (size_t)half * HBH;
        float s1 = 0.f, s2 = 0.f;
        for (int u = lane; u < H; u += 32) {
            float v = ldg_h16(h2h + eoff_h(u, bl));
            s1 += v; s2 += v * v;
        }
        #pragma unroll
        for (int o = 16; o; o >>= 1) {
            s1 += __shfl_xor_sync(0xFFFFFFFFu, s1, o);
            s2 += __shfl_xor_sync(0xFFFFFFFFu, s2, o);
        }
        float mu  = s1 * (1.f / H);
        float var = s2 * (1.f / H) - mu * mu;
        float rs  = rsqrtf(var + 1e-5f);
        float acc = 0.f;
        for (int u = lane; u < H; u += 32) {
            float v  = ldg_h16(h2h + eoff_h(u, bl));
            float hn = (v - mu) * rs * ln_g[u] + ln_b[u];
            acc += hn * Wp[u];
        }
        #pragma unroll
        for (int o = 16; o; o >>= 1) acc += __shfl_xor_sync(0xFFFFFFFFu, acc, o);
        if (lane == 0) out[half * 32 + bl] = acc + bp[0];
    }
}

// ---------------- launch ----------------
extern "C" void kernel_launch(void* const* d_in, const int* in_sizes, int n_in,
                              void* d_out, int out_size) {
    const void*  inp   = d_in[0];
    const float* embed = (const float*)d_in[1];
    const float* Wih   = (const float*)d_in[2];
    const float* Whh   = (const float*)d_in[3];
    const float* bih   = (const float*)d_in[4];
    const float* bhh   = (const float*)d_in[5];
    const float* ln_g  = (const float*)d_in[6];
    const float* ln_b  = (const float*)d_in[7];
    const float* Wp    = (const float*)d_in[8];
    const float* bp    = (const float*)d_in[9];
    float* out = (float*)d_out;

    detect_reset<<<1, 1>>>();
    detect_dtype<<<512, 256>>>((const unsigned*)inp);
    setup_misc<<<512, 256>>>(inp);
    setup_e2<<<128, 256>>>(embed, Wih);

    cudaFuncSetAttribute(lstm_persist, cudaFuncAttributeMaxDynamicSharedMemorySize, SMEM_TOT);
    lstm_persist<<<GRID, NTHREADS, SMEM_TOT>>>(Wih, Whh, bih, bhh, ln_g, ln_b, Wp, bp, out);
}

// round 13
// speedup vs baseline: 2.7614x; 1.2132x over previous
#include <cuda_runtime.h>
#include <cuda_fp16.h>
#include <cstdint>

// ---------------- problem constants ----------------
#define GRID     128
#define NTHREADS 256
#define SQ       2048
#define H        512
#define HBH      16384     // elements per (t, half) plane: 512 units x 32 batches
#define GPLD     34

// smem byte offsets
#define SMEM_SB   0        // 3 staging buffers x 8KB (h fp16), K=128 chunks
#define SMEM_W1   24576    // layer1 Whh fp16: 32KB
#define SMEM_W2   57344    // layer2 (Wih2|Whh2) fp16: 64KB
#define SMEM_GPA  122880   // 32 x GPLD x f32 (layer1 gates)
#define SMEM_GPB  127232   // 32 x GPLD x f32 (layer2 gates)
#define SMEM_E2S  131584   // 16 pairs x 32 rows f32
#define SMEM_BS   133632   // 64 f32 (L1 bias | L2 bias)
#define SMEM_TOT  133888

// ---------------- device scratch ----------------
__device__ __align__(16) __half g_h1h[(SQ + 1) * 2 * HBH];
__device__ __align__(16) __half g_h2h[2 * 2 * HBH];
__device__ __align__(16) float g_E2[16 * 4 * H];
__device__ int      g_pidx[SQ * 64];
__device__ unsigned g_isI32;
__device__ unsigned g_c1[2 * 8 * 32];   // group counters (128B apart)
__device__ unsigned g_c2[2 * 32];       // root counters
__device__ unsigned g_gen[2 * 32];      // per-half generation

__device__ __forceinline__ float sigmoidf_(float x) { return 1.f / (1.f + expf(-x)); }

// element offset inside one (t, half) plane: paired-k 128B rows, XOR swizzle
__device__ __forceinline__ int eoff_h(int k, int b) {
    return (k >> 1) * 64 + (k & 1) * 32 + ((((b >> 3) ^ ((k >> 1) & 3))) << 3) + (b & 7);
}

// ---------------- PTX helpers ----------------
__device__ __forceinline__ void ldmx4t(unsigned* r, uint32_t a) {
    asm volatile("ldmatrix.sync.aligned.m8n8.x4.trans.shared.b16 {%0,%1,%2,%3},[%4];"
                 : "=r"(r[0]), "=r"(r[1]), "=r"(r[2]), "=r"(r[3]) : "r"(a));
}
__device__ __forceinline__ void ldmx2t(unsigned* r, uint32_t a) {
    asm volatile("ldmatrix.sync.aligned.m8n8.x2.trans.shared.b16 {%0,%1},[%2];"
                 : "=r"(r[0]), "=r"(r[1]) : "r"(a));
}
__device__ __forceinline__ void mma16816(float* d, const unsigned* a, const unsigned* b) {
    asm volatile("mma.sync.aligned.m16n8k16.row.col.f32.f16.f16.f32 "
                 "{%0,%1,%2,%3},{%4,%5,%6,%7},{%8,%9},{%0,%1,%2,%3};"
                 : "+f"(d[0]), "+f"(d[1]), "+f"(d[2]), "+f"(d[3])
                 : "r"(a[0]), "r"(a[1]), "r"(a[2]), "r"(a[3]), "r"(b[0]), "r"(b[1]));
}
__device__ __forceinline__ void stg_h16(__half* p, __half v) {
    unsigned short u = *reinterpret_cast<unsigned short*>(&v);
    asm volatile("st.global.cg.u16 [%0], %1;" :: "l"(p), "h"(u) : "memory");
}
__device__ __forceinline__ float ldg_h16(const __half* p) {
    unsigned short u;
    asm volatile("ld.global.cg.u16 %0,[%1];" : "=h"(u) : "l"(p));
    __half b = *reinterpret_cast<__half*>(&u);
    return __half2float(b);
}

// Hierarchical per-half barrier (proven R6/R7/R12). Replay-safe via base snapshot.
__device__ __forceinline__ void half_barrier(unsigned target, int half, int grp) {
    __syncthreads();
    if (threadIdx.x == 0) {
        unsigned* c1 = &g_c1[(half * 8 + grp) * 32];
        unsigned* c2 = &g_c2[half * 32];
        unsigned* gv = &g_gen[half * 32];
        unsigned p1;
        asm volatile("atom.acq_rel.gpu.global.add.u32 %0,[%1],%2;"
                     : "=r"(p1) : "l"(c1), "r"(1u) : "memory");
        bool done = false;
        if (p1 == 7u) {
            asm volatile("st.relaxed.gpu.global.u32 [%0],%1;" :: "l"(c1), "r"(0u) : "memory");
            unsigned p2;
            asm volatile("atom.acq_rel.gpu.global.add.u32 %0,[%1],%2;"
                         : "=r"(p2) : "l"(c2), "r"(1u) : "memory");
            if (p2 == 7u) {
                asm volatile("st.relaxed.gpu.global.u32 [%0],%1;" :: "l"(c2), "r"(0u) : "memory");
                asm volatile("st.release.gpu.global.u32 [%0],%1;" :: "l"(gv), "r"(target) : "memory");
                done = true;
            }
        }
        if (!done) {
            unsigned cur;
            do {
                asm volatile("ld.acquire.gpu.global.u32 %0,[%1];" : "=r"(cur) : "l"(gv) : "memory");
            } while ((int)(cur - target) < 0);
        }
    }
    __syncthreads();
}

// stage one 8KB chunk (K=128 of h fp16); 2 cp.async per thread
__device__ __forceinline__ void stage8(uint32_t sb, const __half* gh, int tid) {
    uint32_t s = sb + (uint32_t)tid * 16u;
    asm volatile("cp.async.cg.shared.global [%0],[%1],16;"
                 :: "r"(s), "l"((const char*)gh + tid * 16) : "memory");
    asm volatile("cp.async.cg.shared.global [%0],[%1],16;"
                 :: "r"(s + 4096u), "l"((const char*)gh + 4096 + tid * 16) : "memory");
}
#define CP_COMMIT() asm volatile("cp.async.commit_group;" ::: "memory")
#define CP_WAIT1()  asm volatile("cp.async.wait_group 1;" ::: "memory")
#define CP_WAIT0()  asm volatile("cp.async.wait_group 0;" ::: "memory")

// ---------------- setup kernels ----------------
__global__ void detect_reset() { g_isI32 = 0u; }

// int64 values in [0,4) -> odd u32 words all zero; int32 -> some nonzero.
__global__ void detect_dtype(const unsigned* __restrict__ w) {
    int i = blockIdx.x * blockDim.x + threadIdx.x;
    if (i < SQ * 64) {
        if ((i & 1) && w[i] != 0u) atomicOr(&g_isI32, 1u);
    }
}

__global__ void setup_misc(const void* __restrict__ inp_raw) {
    int i = blockIdx.x * blockDim.x + threadIdx.x;
    if (i < SQ * 64) {
        int s = i >> 6, b = i & 63;
        long long a, c;
        if (g_isI32) {
            const int* p = (const int*)inp_raw;
            a = p[b * SQ + s];
            c = p[(64 + b) * SQ + s];
        } else {
            const long long* p = (const long long*)inp_raw;
            a = p[(long long)b * SQ + s];
            c = p[(long long)(64 + b) * SQ + s];
        }
        g_pidx[s * 64 + b] = (int)(a * 4 + c);
    }
    __half z = __float2half(0.f);
    if (i < 2 * HBH) g_h1h[i] = z;
    if (i < 4 * HBH) g_h2h[i] = z;
}

__global__ void setup_e2(const float* __restrict__ embed, const float* __restrict__ Wih) {
    int flat = blockIdx.x * blockDim.x + threadIdx.x;
    int p = flat >> 11, r = flat & 2047;
    const float* e0 = embed + (p >> 2) * H;
    const float* e1 = embed + (p & 3) * H;
    const float* w  = Wih + (size_t)r * H;
    float s = 0.f;
    #pragma unroll 4
    for (int k = 0; k < H; k++) s += (e0[k] + e1[k]) * w[k];
    g_E2[p * 2048 + r] = s;
}

// ---------------- persistent merged-layer LSTM kernel ----------------
// CTA = (ug = cta>>1 unit-group 0..63, bh = cta&1 batch half). Interval i:
// layer1[t=i] (i<SQ) and layer2[t=i-1] (i>0), sharing staged h1 slot-i chunks.
// 8 K=128 phases per interval, one sync per phase, lookahead-2 into 3-ring.
__global__ __launch_bounds__(NTHREADS, 1)
void lstm_persist(const float* __restrict__ Wih, const float* __restrict__ Whh,
                  const float* __restrict__ bih, const float* __restrict__ bhh,
                  const float* __restrict__ ln_g, const float* __restrict__ ln_b,
                  const float* __restrict__ Wp,  const float* __restrict__ bp,
                  float* __restrict__ out)
{
    extern __shared__ char smem[];
    __half* w1h = (__half*)(smem + SMEM_W1);
    __half* w2h = (__half*)(smem + SMEM_W2);
    float* gpA = (float*)(smem + SMEM_GPA);
    float* gpB = (float*)(smem + SMEM_GPB);
    float* E2s = (float*)(smem + SMEM_E2S);
    float* bs  = (float*)(smem + SMEM_BS);
    uint32_t su = (uint32_t)__cvta_generic_to_shared(smem);
    const uint32_t SBu = su + SMEM_SB, W1u = su + SMEM_W1, W2u = su + SMEM_W2;
    __shared__ unsigned s_base;

    const int cta  = blockIdx.x;
    const int tid  = threadIdx.x;
    const int warp = tid >> 5, lane = tid & 31;
    const int ug   = cta >> 1;
    const int bh   = cta & 1;
    const int grp  = ug >> 3;
    const int rn = warp >> 1;      // row n8-tile 0..3
    const int bm = warp & 1;       // batch m16-tile 0..1
    const int uu = tid >> 5, bl_e = tid & 31;

    // ldmatrix per-lane offsets (proven R6..R12 formulas)
    const int kA  = (lane & 7) + ((lane & 16) >> 1);
    const int jbA = bm * 2 + ((lane >> 3) & 1);
    const uint32_t aoff = (uint32_t)((kA >> 1) * 128 + (kA & 1) * 64 +
                                     ((jbA ^ ((kA >> 1) & 3)) << 4));
    const int kB  = lane & 15;
    const uint32_t bOff = (uint32_t)((kB >> 1) * 128 + (kB & 1) * 64 +
                                     ((rn ^ ((kB >> 1) & 3)) << 4));
    const int dr = rn * 8 + ((lane & 3) << 1);
    const int dc = bm * 16 + (lane >> 2);

    if (tid == 0) {
        unsigned b_;
        asm volatile("ld.relaxed.gpu.global.u32 %0,[%1];" : "=r"(b_) : "l"(&g_gen[bh * 32]) : "memory");
        s_base = b_;
    }
    __syncthreads();
    unsigned gen = s_base;

    // ======== weight conversion (fp16 hi only): W1 (Whh l0), W2 (Wih1|Whh1) ========
    for (int idx = tid; idx < 32 * H; idx += NTHREADS) {
        int r = idx >> 9, k = idx & (H - 1);
        int R = ((r >> 3) << 9) + (ug << 3) + (r & 7);
        float w = Whh[(size_t)R * H + k];
        int e = (k >> 1) * 64 + (k & 1) * 32 + ((((r >> 3) ^ ((k >> 1) & 3))) << 3) + (r & 7);
        w1h[e] = __float2half(w);
    }
    {
        const float* Wih1 = Wih + (size_t)4 * H * H;
        const float* Whh1 = Whh + (size_t)4 * H * H;
        for (int idx = tid; idx < 32 * 2 * H; idx += NTHREADS) {
            int r = idx >> 10, k = idx & 1023;
            int R = ((r >> 3) << 9) + (ug << 3) + (r & 7);
            float w = (k < H) ? Wih1[(size_t)R * H + k] : Whh1[(size_t)R * H + (k - H)];
            int e = (k >> 1) * 64 + (k & 1) * 32 + ((((r >> 3) ^ ((k >> 1) & 3))) << 3) + (r & 7);
            w2h[e] = __float2half(w);
        }
    }
    for (int idx = tid; idx < 512; idx += NTHREADS) {
        int p = idx >> 5, r = idx & 31;
        int R = ((r >> 3) << 9) + (ug << 3) + (r & 7);
        E2s[idx] = g_E2[p * 2048 + R];
    }
    if (tid < 32) {
        int R = ((tid >> 3) << 9) + (ug << 3) + (tid & 7);
        bs[tid]      = bih[R] + bhh[R];
        bs[tid + 32] = bih[2048 + R] + bhh[2048 + R];
    }
    __syncthreads();

    float cst1 = 0.f, cst2 = 0.f;

    for (int i = 0; i <= SQ; ++i) {
        const bool doL1 = (i < SQ);
        const bool doL2 = (i > 0);
        const int  nch  = doL2 ? 8 : 4;           // K=128 chunks: 4 h1 + 4 h2
        const size_t base1 = (size_t)(i * 2 + bh) * HBH;
        const size_t base2 = (size_t)((((i - 1) & 1)) * 2 + bh) * HBH;

        // prologue: stage chunks 0,1
        #pragma unroll
        for (int n = 0; n < 2; ++n) {
            const __half* gh = (n < 4) ? (g_h1h + base1 + n * 4096)
                                       : (g_h2h + base2 + (n - 4) * 4096);
            stage8(SBu + n * 8192u, gh, tid);
            CP_COMMIT();
        }

        float d1[4] = {0,0,0,0}, d2[4] = {0,0,0,0};

        for (int c = 0; c < nch; ++c) {
            if (c < nch - 1) { CP_WAIT1(); } else { CP_WAIT0(); }
            __syncthreads();                       // chunk c visible; buf (c-1) free

            int n = c + 2;
            if (n < nch) {
                const __half* gh = (n < 4) ? (g_h1h + base1 + n * 4096)
                                           : (g_h2h + base2 + (n - 4) * 4096);
                stage8(SBu + (uint32_t)(n % 3) * 8192u, gh, tid);
                CP_COMMIT();
            }

            uint32_t ab = SBu + (uint32_t)(c % 3) * 8192u + aoff;
            uint32_t b1 = W1u + (uint32_t)c * 8192u + bOff;
            uint32_t b2 = W2u + (uint32_t)c * 8192u + bOff;
            const bool l1 = (c < 4) && doL1;
            #pragma unroll
            for (int t = 0; t < 8; ++t) {
                unsigned Ah[4], Bh_[2];
                ldmx4t(Ah, ab);
                if (l1) {
                    ldmx2t(Bh_, b1);
                    mma16816(d1, Ah, Bh_);
                }
                if (doL2) {
                    ldmx2t(Bh_, b2);
                    mma16816(d2, Ah, Bh_);
                }
                ab += 1024u; b1 += 1024u; b2 += 1024u;
            }
        }

        // write gate partials
        if (doL1) {
            gpA[dr * GPLD + dc]           = d1[0];
            gpA[(dr + 1) * GPLD + dc]     = d1[1];
            gpA[dr * GPLD + dc + 8]       = d1[2];
            gpA[(dr + 1) * GPLD + dc + 8] = d1[3];
        }
        if (doL2) {
            gpB[dr * GPLD + dc]           = d2[0];
            gpB[(dr + 1) * GPLD + dc]     = d2[1];
            gpB[dr * GPLD + dc + 8]       = d2[2];
            gpB[(dr + 1) * GPLD + dc + 8] = d2[3];
        }
        __syncthreads();

        // eltwise layer1
        if (doL1) {
            int p = g_pidx[i * 64 + bh * 32 + bl_e];
            float gv[4];
            #pragma unroll
            for (int gate = 0; gate < 4; ++gate) {
                int r = (gate << 3) + uu;
                gv[gate] = bs[r] + E2s[(p << 5) + r] + gpA[r * GPLD + bl_e];
            }
            float ig = sigmoidf_(gv[0]);
            float fg = sigmoidf_(gv[1]);
            float gg = tanhf(gv[2]);
            float og = sigmoidf_(gv[3]);
            cst1 = fg * cst1 + ig * gg;
            float hv = og * tanhf(cst1);
            size_t off = (size_t)((i + 1) * 2 + bh) * HBH + eoff_h((ug << 3) + uu, bl_e);
            stg_h16(g_h1h + off, __float2half(hv));
        }
        // eltwise layer2
        if (doL2) {
            float gv[4];
            #pragma unroll
            for (int gate = 0; gate < 4; ++gate) {
                int r = (gate << 3) + uu;
                gv[gate] = bs[32 + r] + gpB[r * GPLD + bl_e];
            }
            float ig = sigmoidf_(gv[0]);
            float fg = sigmoidf_(gv[1]);
            float gg = tanhf(gv[2]);
            float og = sigmoidf_(gv[3]);
            cst2 = fg * cst2 + ig * gg;
            float hv = og * tanhf(cst2);
            size_t off = (size_t)((i & 1) * 2 + bh) * HBH + eoff_h((ug << 3) + uu, bl_e);
            stg_h16(g_h2h + off, __float2half(hv));
        }
        half_barrier(++gen, bh, grp);
    }

    // ======== head: LayerNorm + projection (final h2 at parity 0) ========
    if (cta < 8) {
        int half = cta & 1;
        int bl = ((cta >> 1) << 3) + warp;
        const __half* h2h = g_h2h + (size_t)half * HBH;
        float s1 = 0.f, s2 = 0.f;
        for (int u = lane; u < H; u += 32) {
            float v = ldg_h16(h2h + eoff_h(u, bl));
            s1 += v; s2 += v * v;
        }
        #pragma unroll
        for (int o = 16; o; o >>= 1) {
            s1 += __shfl_xor_sync(0xFFFFFFFFu, s1, o);
            s2 += __shfl_xor_sync(0xFFFFFFFFu, s2, o);
        }
        float mu  = s1 * (1.f / H);
        float var = s2 * (1.f / H) - mu * mu;
        float rs  = rsqrtf(var + 1e-5f);
        float acc = 0.f;
        for (int u = lane; u < H; u += 32) {
            float v  = ldg_h16(h2h + eoff_h(u, bl));
            float hn = (v - mu) * rs * ln_g[u] + ln_b[u];
            acc += hn * Wp[u];
        }
        #pragma unroll
        for (int o = 16; o; o >>= 1) acc += __shfl_xor_sync(0xFFFFFFFFu, acc, o);
        if (lane == 0) out[half * 32 + bl] = acc + bp[0];
    }
}

// ---------------- launch ----------------
extern "C" void kernel_launch(void* const* d_in, const int* in_sizes, int n_in,
                              void* d_out, int out_size) {
    const void*  inp   = d_in[0];
    const float* embed = (const float*)d_in[1];
    const float* Wih   = (const float*)d_in[2];
    const float* Whh   = (const float*)d_in[3];
    const float* bih   = (const float*)d_in[4];
    const float* bhh   = (const float*)d_in[5];
    const float* ln_g  = (const float*)d_in[6];
    const float* ln_b  = (const float*)d_in[7];
    const float* Wp    = (const float*)d_in[8];
    const float* bp    = (const float*)d_in[9];
    float* out = (float*)d_out;

    detect_reset<<<1, 1>>>();
    detect_dtype<<<512, 256>>>((const unsigned*)inp);
    setup_misc<<<512, 256>>>(inp);
    setup_e2<<<128, 256>>>(embed, Wih);

    cudaFuncSetAttribute(lstm_persist, cudaFuncAttributeMaxDynamicSharedMemorySize, SMEM_TOT);
    lstm_persist<<<GRID, NTHREADS, SMEM_TOT>>>(Wih, Whh, bih, bhh, ln_g, ln_b, Wp, bp, out);
}

// round 14
// speedup vs baseline: 2.9107x; 1.0541x over previous
#include <cuda_runtime.h>
#include <cuda_fp16.h>
#include <cstdint>

// ---------------- problem constants ----------------
#define GRID     128
#define NTHREADS 512
#define SQ       2048
#define H        512
#define HBH      16384     // elements per (t, half) plane: 512 units x 32 batches
#define GPLD     34

// smem byte offsets
#define SMEM_SB   0        // 3 staging buffers x 16KB (h fp16), K=256 chunks
#define SMEM_W1   49152    // layer1 Whh fp16: 32KB
#define SMEM_W2   81920    // layer2 (Wih2|Whh2) fp16: 64KB
#define SMEM_GPA  147456   // 2 x 32 x GPLD x f32 (layer1 gates, per K-half)
#define SMEM_GPB  156160   // 2 x 32 x GPLD x f32 (layer2 gates, per K-half)
#define SMEM_E2S  164864   // 16 pairs x 32 rows f32
#define SMEM_BS   166912   // 64 f32 (L1 bias | L2 bias)
#define SMEM_TOT  167168

// ---------------- device scratch ----------------
__device__ __align__(16) __half g_h1h[(SQ + 1) * 2 * HBH];
__device__ __align__(16) __half g_h2h[2 * 2 * HBH];
__device__ __align__(16) float g_E2[16 * 4 * H];
__device__ int      g_pidx[SQ * 64];
__device__ unsigned g_isI32;
__device__ unsigned g_c1[2 * 8 * 32];   // group counters (128B apart)
__device__ unsigned g_c2[2 * 32];       // root counters
__device__ unsigned g_gen[2 * 32];      // per-half generation

__device__ __forceinline__ float sigmoidf_(float x) { return 1.f / (1.f + expf(-x)); }

// element offset inside one (t, half) plane: paired-k 128B rows, XOR swizzle
__device__ __forceinline__ int eoff_h(int k, int b) {
    return (k >> 1) * 64 + (k & 1) * 32 + ((((b >> 3) ^ ((k >> 1) & 3))) << 3) + (b & 7);
}

// ---------------- PTX helpers ----------------
__device__ __forceinline__ void ldmx4t(unsigned* r, uint32_t a) {
    asm volatile("ldmatrix.sync.aligned.m8n8.x4.trans.shared.b16 {%0,%1,%2,%3},[%4];"
                 : "=r"(r[0]), "=r"(r[1]), "=r"(r[2]), "=r"(r[3]) : "r"(a));
}
__device__ __forceinline__ void ldmx2t(unsigned* r, uint32_t a) {
    asm volatile("ldmatrix.sync.aligned.m8n8.x2.trans.shared.b16 {%0,%1},[%2];"
                 : "=r"(r[0]), "=r"(r[1]) : "r"(a));
}
__device__ __forceinline__ void mma16816(float* d, const unsigned* a, const unsigned* b) {
    asm volatile("mma.sync.aligned.m16n8k16.row.col.f32.f16.f16.f32 "
                 "{%0,%1,%2,%3},{%4,%5,%6,%7},{%8,%9},{%0,%1,%2,%3};"
                 : "+f"(d[0]), "+f"(d[1]), "+f"(d[2]), "+f"(d[3])
                 : "r"(a[0]), "r"(a[1]), "r"(a[2]), "r"(a[3]), "r"(b[0]), "r"(b[1]));
}
__device__ __forceinline__ void stg_h16(__half* p, __half v) {
    unsigned short u = *reinterpret_cast<unsigned short*>(&v);
    asm volatile("st.global.cg.u16 [%0], %1;" :: "l"(p), "h"(u) : "memory");
}
__device__ __forceinline__ float ldg_h16(const __half* p) {
    unsigned short u;
    asm volatile("ld.global.cg.u16 %0,[%1];" : "=h"(u) : "l"(p));
    __half b = *reinterpret_cast<__half*>(&u);
    return __half2float(b);
}

// Hierarchical per-half barrier (proven R6..R13). Replay-safe via base snapshot.
__device__ __forceinline__ void half_barrier(unsigned target, int half, int grp) {
    __syncthreads();
    if (threadIdx.x == 0) {
        unsigned* c1 = &g_c1[(half * 8 + grp) * 32];
        unsigned* c2 = &g_c2[half * 32];
        unsigned* gv = &g_gen[half * 32];
        unsigned p1;
        asm volatile("atom.acq_rel.gpu.global.add.u32 %0,[%1],%2;"
                     : "=r"(p1) : "l"(c1), "r"(1u) : "memory");
        bool done = false;
        if (p1 == 7u) {
            asm volatile("st.relaxed.gpu.global.u32 [%0],%1;" :: "l"(c1), "r"(0u) : "memory");
            unsigned p2;
            asm volatile("atom.acq_rel.gpu.global.add.u32 %0,[%1],%2;"
                         : "=r"(p2) : "l"(c2), "r"(1u) : "memory");
            if (p2 == 7u) {
                asm volatile("st.relaxed.gpu.global.u32 [%0],%1;" :: "l"(c2), "r"(0u) : "memory");
                asm volatile("st.release.gpu.global.u32 [%0],%1;" :: "l"(gv), "r"(target) : "memory");
                done = true;
            }
        }
        if (!done) {
            unsigned cur;
            do {
                asm volatile("ld.acquire.gpu.global.u32 %0,[%1];" : "=r"(cur) : "l"(gv) : "memory");
            } while ((int)(cur - target) < 0);
        }
    }
    __syncthreads();
}

// stage one 16KB chunk (K=256 of h fp16); 2 cp.async per thread (512 threads)
__device__ __forceinline__ void stage16(uint32_t sb, const __half* gh, int tid) {
    uint32_t s = sb + (uint32_t)tid * 16u;
    asm volatile("cp.async.cg.shared.global [%0],[%1],16;"
                 :: "r"(s), "l"((const char*)gh + tid * 16) : "memory");
    asm volatile("cp.async.cg.shared.global [%0],[%1],16;"
                 :: "r"(s + 8192u), "l"((const char*)gh + 8192 + tid * 16) : "memory");
}
#define CP_COMMIT() asm volatile("cp.async.commit_group;" ::: "memory")
#define CP_WAIT1()  asm volatile("cp.async.wait_group 1;" ::: "memory")
#define CP_WAIT0()  asm volatile("cp.async.wait_group 0;" ::: "memory")

// ---------------- setup kernels ----------------
__global__ void detect_reset() { g_isI32 = 0u; }

// int64 values in [0,4) -> odd u32 words all zero; int32 -> some nonzero.
__global__ void detect_dtype(const unsigned* __restrict__ w) {
    int i = blockIdx.x * blockDim.x + threadIdx.x;
    if (i < SQ * 64) {
        if ((i & 1) && w[i] != 0u) atomicOr(&g_isI32, 1u);
    }
}

__global__ void setup_misc(const void* __restrict__ inp_raw) {
    int i = blockIdx.x * blockDim.x + threadIdx.x;
    if (i < SQ * 64) {
        int s = i >> 6, b = i & 63;
        long long a, c;
        if (g_isI32) {
            const int* p = (const int*)inp_raw;
            a = p[b * SQ + s];
            c = p[(64 + b) * SQ + s];
        } else {
            const long long* p = (const long long*)inp_raw;
            a = p[(long long)b * SQ + s];
            c = p[(long long)(64 + b) * SQ + s];
        }
        g_pidx[s * 64 + b] = (int)(a * 4 + c);
    }
    __half z = __float2half(0.f);
    if (i < 2 * HBH) g_h1h[i] = z;
    if (i < 4 * HBH) g_h2h[i] = z;
}

__global__ void setup_e2(const float* __restrict__ embed, const float* __restrict__ Wih) {
    int flat = blockIdx.x * blockDim.x + threadIdx.x;
    int p = flat >> 11, r = flat & 2047;
    const float* e0 = embed + (p >> 2) * H;
    const float* e1 = embed + (p & 3) * H;
    const float* w  = Wih + (size_t)r * H;
    float s = 0.f;
    #pragma unroll 4
    for (int k = 0; k < H; k++) s += (e0[k] + e1[k]) * w[k];
    g_E2[p * 2048 + r] = s;
}

// ---------------- persistent merged-layer LSTM kernel ----------------
// CTA = (ug = cta>>1 unit-group 0..63, bh = cta&1 batch half). Interval i:
// layer1[t=i] (i<SQ) and layer2[t=i-1] (i>0), sharing staged h1 slot-i chunks.
// 4 K=256 phases per interval; 16 warps = (ks x rn x bm), K split across ks.
__global__ __launch_bounds__(NTHREADS, 1)
void lstm_persist(const float* __restrict__ Wih, const float* __restrict__ Whh,
                  const float* __restrict__ bih, const float* __restrict__ bhh,
                  const float* __restrict__ ln_g, const float* __restrict__ ln_b,
                  const float* __restrict__ Wp,  const float* __restrict__ bp,
                  float* __restrict__ out)
{
    extern __shared__ char smem[];
    __half* w1h = (__half*)(smem + SMEM_W1);
    __half* w2h = (__half*)(smem + SMEM_W2);
    float* gpA = (float*)(smem + SMEM_GPA);     // [2][32][GPLD]
    float* gpB = (float*)(smem + SMEM_GPB);     // [2][32][GPLD]
    float* E2s = (float*)(smem + SMEM_E2S);
    float* bs  = (float*)(smem + SMEM_BS);
    uint32_t su = (uint32_t)__cvta_generic_to_shared(smem);
    const uint32_t SBu = su + SMEM_SB, W1u = su + SMEM_W1, W2u = su + SMEM_W2;
    __shared__ unsigned s_base;

    const int cta  = blockIdx.x;
    const int tid  = threadIdx.x;
    const int warp = tid >> 5, lane = tid & 31;
    const int ug   = cta >> 1;
    const int bh   = cta & 1;
    const int grp  = ug >> 3;
    const int ks = warp >> 3;          // K-half 0..1
    const int rn = (warp >> 1) & 3;    // row n8-tile 0..3
    const int bm = warp & 1;           // batch m16-tile 0..1
    const int uu = tid >> 5, bl_e = tid & 31;   // eltwise map (tid<256)

    // ldmatrix per-lane offsets (proven R6..R13 formulas)
    const int kA  = (lane & 7) + ((lane & 16) >> 1);
    const int jbA = bm * 2 + ((lane >> 3) & 1);
    const uint32_t aoff = (uint32_t)((kA >> 1) * 128 + (kA & 1) * 64 +
                                     ((jbA ^ ((kA >> 1) & 3)) << 4));
    const int kB  = lane & 15;
    const uint32_t bOff = (uint32_t)((kB >> 1) * 128 + (kB & 1) * 64 +
                                     ((rn ^ ((kB >> 1) & 3)) << 4));
    const int dr = rn * 8 + ((lane & 3) << 1);
    const int dc = bm * 16 + (lane >> 2);
    float* gpA_w = gpA + ks * 32 * GPLD;
    float* gpB_w = gpB + ks * 32 * GPLD;

    if (tid == 0) {
        unsigned b_;
        asm volatile("ld.relaxed.gpu.global.u32 %0,[%1];" : "=r"(b_) : "l"(&g_gen[bh * 32]) : "memory");
        s_base = b_;
    }
    __syncthreads();
    unsigned gen = s_base;

    // ======== weight conversion (fp16): W1 (Whh l0), W2 (Wih1|Whh1) ========
    for (int idx = tid; idx < 32 * H; idx += NTHREADS) {
        int r = idx >> 9, k = idx & (H - 1);
        int R = ((r >> 3) << 9) + (ug << 3) + (r & 7);
        float w = Whh[(size_t)R * H + k];
        int e = (k >> 1) * 64 + (k & 1) * 32 + ((((r >> 3) ^ ((k >> 1) & 3))) << 3) + (r & 7);
        w1h[e] = __float2half(w);
    }
    {
        const float* Wih1 = Wih + (size_t)4 * H * H;
        const float* Whh1 = Whh + (size_t)4 * H * H;
        for (int idx = tid; idx < 32 * 2 * H; idx += NTHREADS) {
            int r = idx >> 10, k = idx & 1023;
            int R = ((r >> 3) << 9) + (ug << 3) + (r & 7);
            float w = (k < H) ? Wih1[(size_t)R * H + k] : Whh1[(size_t)R * H + (k - H)];
            int e = (k >> 1) * 64 + (k & 1) * 32 + ((((r >> 3) ^ ((k >> 1) & 3))) << 3) + (r & 7);
            w2h[e] = __float2half(w);
        }
    }
    for (int idx = tid; idx < 512; idx += NTHREADS) {
        int p = idx >> 5, r = idx & 31;
        int R = ((r >> 3) << 9) + (ug << 3) + (r & 7);
        E2s[idx] = g_E2[p * 2048 + R];
    }
    if (tid < 32) {
        int R = ((tid >> 3) << 9) + (ug << 3) + (tid & 7);
        bs[tid]      = bih[R] + bhh[R];
        bs[tid + 32] = bih[2048 + R] + bhh[2048 + R];
    }
    __syncthreads();

    float cst1 = 0.f, cst2 = 0.f;

    for (int i = 0; i <= SQ; ++i) {
        const bool doL1 = (i < SQ);
        const bool doL2 = (i > 0);
        const int  nch  = doL2 ? 4 : 2;            // K=256 chunks: 2 h1 + 2 h2
        const size_t base1 = (size_t)(i * 2 + bh) * HBH;
        const size_t base2 = (size_t)((((i - 1) & 1)) * 2 + bh) * HBH;

        // prologue: stage chunks 0,1
        #pragma unroll
        for (int n = 0; n < 2; ++n) {
            const __half* gh = (n < 2) ? (g_h1h + base1 + n * 8192)
                                       : (g_h2h + base2 + (n - 2) * 8192);
            stage16(SBu + n * 16384u, gh, tid);
            CP_COMMIT();
        }

        float d1[4] = {0,0,0,0}, d2[4] = {0,0,0,0};

        for (int c = 0; c < nch; ++c) {
            if (c < nch - 1) { CP_WAIT1(); } else { CP_WAIT0(); }
            __syncthreads();                       // chunk c visible; buf (c-1) free

            int n = c + 2;
            if (n < nch) {
                const __half* gh = (n < 2) ? (g_h1h + base1 + n * 8192)
                                           : (g_h2h + base2 + (n - 2) * 8192);
                stage16(SBu + (uint32_t)(n % 3) * 16384u, gh, tid);
                CP_COMMIT();
            }

            uint32_t ab = SBu + (uint32_t)(c % 3) * 16384u + (uint32_t)ks * 8192u + aoff;
            uint32_t b1 = W1u + (uint32_t)c * 16384u + (uint32_t)ks * 8192u + bOff;
            uint32_t b2 = W2u + (uint32_t)c * 16384u + (uint32_t)ks * 8192u + bOff;
            const bool l1 = (c < 2) && doL1;
            #pragma unroll
            for (int t = 0; t < 8; ++t) {
                unsigned Ah[4], Bh_[2];
                ldmx4t(Ah, ab);
                if (l1) {
                    ldmx2t(Bh_, b1);
                    mma16816(d1, Ah, Bh_);
                }
                if (doL2) {
                    ldmx2t(Bh_, b2);
                    mma16816(d2, Ah, Bh_);
                }
                ab += 1024u; b1 += 1024u; b2 += 1024u;
            }
        }

        // write gate partials (per K-half)
        if (doL1) {
            gpA_w[dr * GPLD + dc]           = d1[0];
            gpA_w[(dr + 1) * GPLD + dc]     = d1[1];
            gpA_w[dr * GPLD + dc + 8]       = d1[2];
            gpA_w[(dr + 1) * GPLD + dc + 8] = d1[3];
        }
        if (doL2) {
            gpB_w[dr * GPLD + dc]           = d2[0];
            gpB_w[(dr + 1) * GPLD + dc]     = d2[1];
            gpB_w[dr * GPLD + dc + 8]       = d2[2];
            gpB_w[(dr + 1) * GPLD + dc + 8] = d2[3];
        }
        __syncthreads();

        if (tid < 256) {
            // eltwise layer1
            if (doL1) {
                int p = g_pidx[i * 64 + bh * 32 + bl_e];
                float gv[4];
                #pragma unroll
                for (int gate = 0; gate < 4; ++gate) {
                    int r = (gate << 3) + uu;
                    gv[gate] = bs[r] + E2s[(p << 5) + r]
                             + gpA[r * GPLD + bl_e] + gpA[(32 + r) * GPLD + bl_e];
                }
                float ig = sigmoidf_(gv[0]);
                float fg = sigmoidf_(gv[1]);
                float gg = tanhf(gv[2]);
                float og = sigmoidf_(gv[3]);
                cst1 = fg * cst1 + ig * gg;
                float hv = og * tanhf(cst1);
                size_t off = (size_t)((i + 1) * 2 + bh) * HBH + eoff_h((ug << 3) + uu, bl_e);
                stg_h16(g_h1h + off, __float2half(hv));
            }
            // eltwise layer2
            if (doL2) {
                float gv[4];
                #pragma unroll
                for (int gate = 0; gate < 4; ++gate) {
                    int r = (gate << 3) + uu;
                    gv[gate] = bs[32 + r]
                             + gpB[r * GPLD + bl_e] + gpB[(32 + r) * GPLD + bl_e];
                }
                float ig = sigmoidf_(gv[0]);
                float fg = sigmoidf_(gv[1]);
                float gg = tanhf(gv[2]);
                float og = sigmoidf_(gv[3]);
                cst2 = fg * cst2 + ig * gg;
                float hv = og * tanhf(cst2);
                size_t off = (size_t)((i & 1) * 2 + bh) * HBH + eoff_h((ug << 3) + uu, bl_e);
                stg_h16(g_h2h + off, __float2half(hv));
            }
        }
        half_barrier(++gen, bh, grp);
    }

    // ======== head: LayerNorm + projection (final h2 at parity 0) ========
    if (cta < 8 && warp < 8) {
        int half = cta & 1;
        int bl = ((cta >> 1) << 3) + warp;
        const __half* h2h = g_h2h + (size_t)half * HBH;
        float s1 = 0.f, s2 = 0.f;
        for (int u = lane; u < H; u += 32) {
            float v = ldg_h16(h2h + eoff_h(u, bl));
            s1 += v; s2 += v * v;
        }
        #pragma unroll
        for (int o = 16; o; o >>= 1) {
            s1 += __shfl_xor_sync(0xFFFFFFFFu, s1, o);
            s2 += __shfl_xor_sync(0xFFFFFFFFu, s2, o);
        }
        float mu  = s1 * (1.f / H);
        float var = s2 * (1.f / H) - mu * mu;
        float rs  = rsqrtf(var + 1e-5f);
        float acc = 0.f;
        for (int u = lane; u < H; u += 32) {
            float v  = ldg_h16(h2h + eoff_h(u, bl));
            float hn = (v - mu) * rs * ln_g[u] + ln_b[u];
            acc += hn * Wp[u];
        }
        #pragma unroll
        for (int o = 16; o; o >>= 1) acc += __shfl_xor_sync(0xFFFFFFFFu, acc, o);
        if (lane == 0) out[half * 32 + bl] = acc + bp[0];
    }
}

// ---------------- launch ----------------
extern "C" void kernel_launch(void* const* d_in, const int* in_sizes, int n_in,
                              void* d_out, int out_size) {
    const void*  inp   = d_in[0];
    const float* embed = (const float*)d_in[1];
    const float* Wih   = (const float*)d_in[2];
    const float* Whh   = (const float*)d_in[3];
    const float* bih   = (const float*)d_in[4];
    const float* bhh   = (const float*)d_in[5];
    const float* ln_g  = (const float*)d_in[6];
    const float* ln_b  = (const float*)d_in[7];
    const float* Wp    = (const float*)d_in[8];
    const float* bp    = (const float*)d_in[9];
    float* out = (float*)d_out;

    detect_reset<<<1, 1>>>();
    detect_dtype<<<512, 256>>>((const unsigned*)inp);
    setup_misc<<<512, 256>>>(inp);
    setup_e2<<<128, 256>>>(embed, Wih);

    cudaFuncSetAttribute(lstm_persist, cudaFuncAttributeMaxDynamicSharedMemorySize, SMEM_TOT);
    lstm_persist<<<GRID, NTHREADS, SMEM_TOT>>>(Wih, Whh, bih, bhh, ln_g, ln_b, Wp, bp, out);
}